// round 4
// baseline (speedup 1.0000x reference)
#include <cuda_runtime.h>
#include <cuda_bf16.h>

// ---------------------------------------------------------------------------
// MultiHead2DAttention (Shaw relative positions, T2T variant)
// B=2, L=1024, D=1024, H=16, DH=64, M=64, R=129
//
// Pipeline (8 launches, all on default stream, graph-capturable):
//   1-3) q = x@Wq * 0.125 ; k = x@Wk ; v = x@Wv        (SGEMM 2048x1024x1024)
//   4)   relq[bh,i,r] = q[bh,i,:] . rel_k_table[r,:]    ([32][1024][129])
//   5)   S[bh,i,j]    = q.k + relq[bh,i,clip(j-i)+64]   (128MB scratch)
//   6)   softmax rows in-place + wsum[bh,i,r]           (fused, row per CTA)
//   7)   O = W@V + wsum@rel_v_table                     (per-head GEMM + epi)
//   8)   out = O @ Wo                                   (SGEMM)
// ---------------------------------------------------------------------------

namespace {
constexpr int B  = 2;
constexpr int L  = 1024;
constexpr int D  = 1024;
constexpr int H  = 16;
constexpr int DH = 64;
constexpr int MREL = 64;
constexpr int R  = 2 * MREL + 1;   // 129
constexpr int NT = B * L;          // 2048
constexpr int BH = B * H;          // 32
}

// Scratch buffers (device globals: no allocations allowed)
__device__ float g_q[NT * D];
__device__ float g_k[NT * D];
__device__ float g_v[NT * D];
__device__ float g_o[NT * D];
__device__ float g_relq[(size_t)BH * L * R];   // 4.2M floats
__device__ float g_s[(size_t)BH * L * L];      // 33.5M floats (128 MB)
__device__ float g_wsum[(size_t)BH * L * R];   // 4.2M floats

// ---------------------------------------------------------------------------
// SGEMM: C[M,N] = alpha * A[M,K] @ B[K,N], row-major.
// 128x128 tile, BK=8, 256 threads, 8x8 microtile per thread.
// Requires M%128==0, N%128==0, K%8==0.
// ---------------------------------------------------------------------------
__global__ __launch_bounds__(256) void sgemm128(const float* __restrict__ A,
                                                const float* __restrict__ Bm,
                                                float* __restrict__ C,
                                                int Md, int Nd, int Kd,
                                                float alpha) {
    __shared__ __align__(16) float As[8][128];
    __shared__ __align__(16) float Bs[8][128];

    const int tid = threadIdx.x;
    const int bm = blockIdx.y * 128;
    const int bn = blockIdx.x * 128;
    const int tx = tid & 15;
    const int ty = tid >> 4;

    // A-tile load mapping: 128 rows x 8 cols, one float4 per thread
    const int ar = tid >> 1;
    const int ac = (tid & 1) * 4;
    // B-tile load mapping: 8 rows x 128 cols, one float4 per thread
    const int br = tid >> 5;
    const int bc = (tid & 31) * 4;

    const float* Ap = A + (size_t)(bm + ar) * Kd + ac;
    const float* Bp = Bm + (size_t)br * Nd + bn + bc;

    float acc[8][8];
#pragma unroll
    for (int i = 0; i < 8; ++i)
#pragma unroll
        for (int j = 0; j < 8; ++j) acc[i][j] = 0.0f;

    for (int k0 = 0; k0 < Kd; k0 += 8) {
        float4 av = *(const float4*)(Ap + k0);
        float4 bv = *(const float4*)(Bp + (size_t)k0 * Nd);
        As[ac + 0][ar] = av.x;
        As[ac + 1][ar] = av.y;
        As[ac + 2][ar] = av.z;
        As[ac + 3][ar] = av.w;
        *(float4*)&Bs[br][bc] = bv;
        __syncthreads();

#pragma unroll
        for (int k = 0; k < 8; ++k) {
            float a[8], bb[8];
            *(float4*)&a[0]  = *(const float4*)&As[k][ty * 8];
            *(float4*)&a[4]  = *(const float4*)&As[k][ty * 8 + 4];
            *(float4*)&bb[0] = *(const float4*)&Bs[k][tx * 8];
            *(float4*)&bb[4] = *(const float4*)&Bs[k][tx * 8 + 4];
#pragma unroll
            for (int i = 0; i < 8; ++i)
#pragma unroll
                for (int j = 0; j < 8; ++j) acc[i][j] += a[i] * bb[j];
        }
        __syncthreads();
    }

#pragma unroll
    for (int i = 0; i < 8; ++i) {
        float* cp = C + (size_t)(bm + ty * 8 + i) * Nd + bn + tx * 8;
        float4 o0 = make_float4(acc[i][0] * alpha, acc[i][1] * alpha,
                                acc[i][2] * alpha, acc[i][3] * alpha);
        float4 o1 = make_float4(acc[i][4] * alpha, acc[i][5] * alpha,
                                acc[i][6] * alpha, acc[i][7] * alpha);
        *(float4*)cp = o0;
        *(float4*)(cp + 4) = o1;
    }
}

// ---------------------------------------------------------------------------
// relq[bh,i,r] = sum_d q[bh,i,d] * rel_k_table[r,d]
// grid: (L/32, BH); 256 threads. 32 q-rows + full table in smem.
// ---------------------------------------------------------------------------
__global__ __launch_bounds__(256) void relq_kernel(const float* __restrict__ relk) {
    __shared__ float qs[32][64];
    __shared__ float ts[R][65];   // padded: avoid stride-64 bank conflicts

    const int tid = threadIdx.x;
    const int bh = blockIdx.y;
    const int b = bh >> 4;
    const int h = bh & 15;
    const int i0 = blockIdx.x * 32;

    for (int e = tid; e < 32 * 64; e += 256) {
        int i = e >> 6, d = e & 63;
        qs[i][d] = g_q[(size_t)(b * L + i0 + i) * D + h * DH + d];
    }
    for (int e = tid; e < R * 64; e += 256) {
        ts[e >> 6][e & 63] = relk[e];
    }
    __syncthreads();

    for (int e = tid; e < 32 * R; e += 256) {
        int i = e / R;
        int r = e % R;
        float s = 0.0f;
#pragma unroll
        for (int d = 0; d < 64; ++d) s += qs[i][d] * ts[r][d];
        g_relq[((size_t)bh * L + i0 + i) * R + r] = s;
    }
}

// ---------------------------------------------------------------------------
// Logits: S[bh,i,j] = q_i . k_j + relq[bh,i,clip(j-i)+64]
// grid: (L/64 j-blocks, L/64 i-blocks, BH); 256 threads, 4x4 microtile.
// ---------------------------------------------------------------------------
__global__ __launch_bounds__(256) void logits_kernel() {
    __shared__ __align__(16) float Qs[64][68];  // Qs[d][i]
    __shared__ __align__(16) float Ks[64][68];  // Ks[d][j]

    const int tid = threadIdx.x;
    const int bh = blockIdx.z;
    const int b = bh >> 4;
    const int h = bh & 15;
    const int i0 = blockIdx.y * 64;
    const int j0 = blockIdx.x * 64;
    const int tx = tid & 15;
    const int ty = tid >> 4;

    // cooperative transposed loads: row = tid/4, 4 float4 segments
    const int rI = tid >> 2;
    const int seg = (tid & 3) * 16;

    const float* qb = g_q + (size_t)(b * L + i0 + rI) * D + h * DH + seg;
    const float* kb = g_k + (size_t)(b * L + j0 + rI) * D + h * DH + seg;
#pragma unroll
    for (int u = 0; u < 4; ++u) {
        float4 v = *(const float4*)(qb + 4 * u);
        int c = seg + 4 * u;
        Qs[c + 0][rI] = v.x; Qs[c + 1][rI] = v.y;
        Qs[c + 2][rI] = v.z; Qs[c + 3][rI] = v.w;
        float4 w = *(const float4*)(kb + 4 * u);
        Ks[c + 0][rI] = w.x; Ks[c + 1][rI] = w.y;
        Ks[c + 2][rI] = w.z; Ks[c + 3][rI] = w.w;
    }
    __syncthreads();

    float acc[4][4];
#pragma unroll
    for (int i = 0; i < 4; ++i)
#pragma unroll
        for (int j = 0; j < 4; ++j) acc[i][j] = 0.0f;

#pragma unroll 16
    for (int d = 0; d < 64; ++d) {
        float4 a = *(const float4*)&Qs[d][ty * 4];
        float4 bq = *(const float4*)&Ks[d][tx * 4];
        float av[4] = {a.x, a.y, a.z, a.w};
        float bv[4] = {bq.x, bq.y, bq.z, bq.w};
#pragma unroll
        for (int i = 0; i < 4; ++i)
#pragma unroll
            for (int j = 0; j < 4; ++j) acc[i][j] += av[i] * bv[j];
    }

    const int gj0 = j0 + tx * 4;
#pragma unroll
    for (int ii = 0; ii < 4; ++ii) {
        const int gi = i0 + ty * 4 + ii;
        const float* rq = g_relq + ((size_t)bh * L + gi) * R;
        float4 o;
        int r0 = min(max(gj0 + 0 - gi, -MREL), MREL) + MREL;
        int r1 = min(max(gj0 + 1 - gi, -MREL), MREL) + MREL;
        int r2 = min(max(gj0 + 2 - gi, -MREL), MREL) + MREL;
        int r3 = min(max(gj0 + 3 - gi, -MREL), MREL) + MREL;
        o.x = acc[ii][0] + rq[r0];
        o.y = acc[ii][1] + rq[r1];
        o.z = acc[ii][2] + rq[r2];
        o.w = acc[ii][3] + rq[r3];
        *(float4*)(g_s + ((size_t)bh * L + gi) * L + gj0) = o;
    }
}

// ---------------------------------------------------------------------------
// Fused softmax + wsum. One CTA (256 threads) per (bh,i) row.
//   wsum[0]   = sum_{j<=i-64} w[j]
//   wsum[r]   = w[i+r-64]            (1<=r<=127, if in range else 0)
//   wsum[128] = sum_{j>=i+64} w[j]
// ---------------------------------------------------------------------------
__global__ __launch_bounds__(256) void softmax_kernel() {
    __shared__ __align__(16) float sw[L];
    __shared__ float red[256];

    const int row = blockIdx.x;     // bh*L + i
    const int i = row & (L - 1);
    const int tid = threadIdx.x;
    float* srow_g = g_s + (size_t)row * L;

    float4 x4 = *(const float4*)(srow_g + tid * 4);

    // row max
    float m = fmaxf(fmaxf(x4.x, x4.y), fmaxf(x4.z, x4.w));
    red[tid] = m;
    __syncthreads();
    for (int s = 128; s > 0; s >>= 1) {
        if (tid < s) red[tid] = fmaxf(red[tid], red[tid + s]);
        __syncthreads();
    }
    const float rowmax = red[0];
    __syncthreads();

    x4.x = expf(x4.x - rowmax);
    x4.y = expf(x4.y - rowmax);
    x4.z = expf(x4.z - rowmax);
    x4.w = expf(x4.w - rowmax);

    red[tid] = x4.x + x4.y + x4.z + x4.w;
    __syncthreads();
    for (int s = 128; s > 0; s >>= 1) {
        if (tid < s) red[tid] += red[tid + s];
        __syncthreads();
    }
    const float inv = 1.0f / red[0];
    __syncthreads();

    x4.x *= inv; x4.y *= inv; x4.z *= inv; x4.w *= inv;
    *(float4*)(sw + tid * 4) = x4;
    *(float4*)(srow_g + tid * 4) = x4;
    __syncthreads();

    // head: j in [0, i-64], tail: j in [i+64, L-1]
    const int headEnd = i - MREL;    // inclusive
    const int tailStart = i + MREL;  // inclusive
    float hp = 0.0f, tp = 0.0f;
    for (int j = tid; j <= headEnd; j += 256) hp += sw[j];
    for (int j = tailStart + tid; j < L; j += 256) tp += sw[j];

    red[tid] = hp;
    __syncthreads();
    for (int s = 128; s > 0; s >>= 1) {
        if (tid < s) red[tid] += red[tid + s];
        __syncthreads();
    }
    const float head = red[0];
    __syncthreads();

    red[tid] = tp;
    __syncthreads();
    for (int s = 128; s > 0; s >>= 1) {
        if (tid < s) red[tid] += red[tid + s];
        __syncthreads();
    }
    const float tail = red[0];
    __syncthreads();

    if (tid < R) {
        float val;
        if (tid == 0) {
            val = head;
        } else if (tid == R - 1) {
            val = tail;
        } else {
            int j = i + tid - MREL;
            val = (j >= 0 && j < L) ? sw[j] : 0.0f;
        }
        g_wsum[(size_t)row * R + tid] = val;
    }
}

// ---------------------------------------------------------------------------
// Attention output: O[bh] = W[1024,1024] @ V[1024,64] + wsum[1024,129] @ T[129,64]
// grid: (L/64 i-blocks, BH); 256 threads, 4x4 microtile (64 i x 64 d tile).
// Writes directly into combined-head layout g_o[(b,i), h*64+d].
// ---------------------------------------------------------------------------
__global__ __launch_bounds__(256) void attnout_kernel(const float* __restrict__ relv) {
    __shared__ __align__(16) float sbuf[2 * 64 * 68];
    float (*Ws)[68] = (float(*)[68])sbuf;               // Ws[k][i]
    float (*Vs)[68] = (float(*)[68])(sbuf + 64 * 68);   // Vs[k][d]

    const int tid = threadIdx.x;
    const int bh = blockIdx.y;
    const int b = bh >> 4;
    const int h = bh & 15;
    const int i0 = blockIdx.x * 64;
    const int tx = tid & 15;
    const int ty = tid >> 4;

    const int rI = tid >> 2;
    const int seg = (tid & 3) * 16;

    float acc[4][4];
#pragma unroll
    for (int i = 0; i < 4; ++i)
#pragma unroll
        for (int j = 0; j < 4; ++j) acc[i][j] = 0.0f;

    for (int k0 = 0; k0 < L; k0 += 64) {
        // W block (rows i0.., cols k0..) -> transposed into Ws[k][i]
        const float* wb = g_s + ((size_t)bh * L + i0 + rI) * L + k0 + seg;
#pragma unroll
        for (int u = 0; u < 4; ++u) {
            float4 v = *(const float4*)(wb + 4 * u);
            int c = seg + 4 * u;
            Ws[c + 0][rI] = v.x; Ws[c + 1][rI] = v.y;
            Ws[c + 2][rI] = v.z; Ws[c + 3][rI] = v.w;
        }
        // V block natural layout: Vs[k][d]
        const float* vb = g_v + (size_t)(b * L + k0 + rI) * D + h * DH + seg;
#pragma unroll
        for (int u = 0; u < 4; ++u)
            *(float4*)&Vs[rI][seg + 4 * u] = *(const float4*)(vb + 4 * u);
        __syncthreads();

#pragma unroll 16
        for (int k = 0; k < 64; ++k) {
            float4 a = *(const float4*)&Ws[k][ty * 4];
            float4 bq = *(const float4*)&Vs[k][tx * 4];
            float av[4] = {a.x, a.y, a.z, a.w};
            float bv[4] = {bq.x, bq.y, bq.z, bq.w};
#pragma unroll
            for (int i = 0; i < 4; ++i)
#pragma unroll
                for (int j = 0; j < 4; ++j) acc[i][j] += av[i] * bv[j];
        }
        __syncthreads();
    }

    // rel_v epilogue: stage T[129][64] into sbuf with pad 65 (8385 <= 8704)
    for (int e = tid; e < R * 64; e += 256)
        sbuf[(e >> 6) * 65 + (e & 63)] = relv[e];
    __syncthreads();

    const float* wsrow[4];
#pragma unroll
    for (int ii = 0; ii < 4; ++ii)
        wsrow[ii] = g_wsum + ((size_t)bh * L + i0 + ty * 4 + ii) * R;

    for (int r = 0; r < R; ++r) {
        const float t0 = sbuf[r * 65 + tx * 4 + 0];
        const float t1 = sbuf[r * 65 + tx * 4 + 1];
        const float t2 = sbuf[r * 65 + tx * 4 + 2];
        const float t3 = sbuf[r * 65 + tx * 4 + 3];
#pragma unroll
        for (int ii = 0; ii < 4; ++ii) {
            const float w = __ldg(&wsrow[ii][r]);
            acc[ii][0] += w * t0;
            acc[ii][1] += w * t1;
            acc[ii][2] += w * t2;
            acc[ii][3] += w * t3;
        }
    }

#pragma unroll
    for (int ii = 0; ii < 4; ++ii) {
        float4 o = make_float4(acc[ii][0], acc[ii][1], acc[ii][2], acc[ii][3]);
        *(float4*)(g_o + (size_t)(b * L + i0 + ty * 4 + ii) * D + h * DH + tx * 4) = o;
    }
}

// ---------------------------------------------------------------------------
// Launch
// ---------------------------------------------------------------------------
extern "C" void kernel_launch(void* const* d_in, const int* in_sizes, int n_in,
                              void* d_out, int out_size) {
    const float* x    = (const float*)d_in[0];
    const float* Wq   = (const float*)d_in[1];
    const float* Wk   = (const float*)d_in[2];
    const float* Wv   = (const float*)d_in[3];
    const float* Wo   = (const float*)d_in[4];
    const float* relk = (const float*)d_in[5];
    const float* relv = (const float*)d_in[6];
    float* out = (float*)d_out;

    float *pq, *pk, *pv, *po;
    cudaGetSymbolAddress((void**)&pq, g_q);
    cudaGetSymbolAddress((void**)&pk, g_k);
    cudaGetSymbolAddress((void**)&pv, g_v);
    cudaGetSymbolAddress((void**)&po, g_o);

    const dim3 gg(D / 128, NT / 128);   // (8, 16)
    const float qscale = 0.125f;        // DH^-0.5 = 1/8

    sgemm128<<<gg, 256>>>(x, Wq, pq, NT, D, D, qscale);
    sgemm128<<<gg, 256>>>(x, Wk, pk, NT, D, D, 1.0f);
    sgemm128<<<gg, 256>>>(x, Wv, pv, NT, D, D, 1.0f);

    relq_kernel<<<dim3(L / 32, BH), 256>>>(relk);

    logits_kernel<<<dim3(L / 64, L / 64, BH), 256>>>();

    softmax_kernel<<<BH * L, 256>>>();

    attnout_kernel<<<dim3(L / 64, BH), 256>>>(relv);

    sgemm128<<<gg, 256>>>(po, Wo, out, NT, D, D, 1.0f);
}

// round 5
// speedup vs baseline: 1.2138x; 1.2138x over previous
#include <cuda_runtime.h>
#include <cuda_bf16.h>

// ---------------------------------------------------------------------------
// MultiHead2DAttention (Shaw relative positions, T2T variant)
// B=2, L=1024, D=1024, H=16, DH=64, M=64, R=129
// Round 4: all GEMM-like inner loops rewritten with packed fp32 FMA
// (fma.rn.f32x2) -> 2x fp32 pipe throughput, exact fp32 semantics.
// ---------------------------------------------------------------------------

namespace {
constexpr int B  = 2;
constexpr int L  = 1024;
constexpr int D  = 1024;
constexpr int H  = 16;
constexpr int DH = 64;
constexpr int MREL = 64;
constexpr int R  = 2 * MREL + 1;   // 129
constexpr int RP = 132;            // padded row stride for relq/wsum (float4-aligned)
constexpr int NT = B * L;          // 2048
constexpr int BH = B * H;          // 32
}

// Scratch buffers (device globals: no allocations allowed)
__device__ float g_q[NT * D];
__device__ float g_k[NT * D];
__device__ float g_v[NT * D];
__device__ float g_o[NT * D];
__device__ float g_relq[(size_t)BH * L * RP];
__device__ float g_s[(size_t)BH * L * L];      // 128 MB
__device__ float g_wsum[(size_t)BH * L * RP];

// ---------------------------------------------------------------------------
// packed fp32 helpers
// ---------------------------------------------------------------------------
typedef unsigned long long u64;

__device__ __forceinline__ u64 pk2(float x, float y) {
    u64 r;
    asm("mov.b64 %0, {%1, %2};" : "=l"(r) : "f"(x), "f"(y));
    return r;
}
__device__ __forceinline__ u64 dup2(float x) { return pk2(x, x); }
__device__ __forceinline__ u64 ffma2(u64 a, u64 b, u64 c) {
    u64 d;
    asm("fma.rn.f32x2 %0, %1, %2, %3;" : "=l"(d) : "l"(a), "l"(b), "l"(c));
    return d;
}
__device__ __forceinline__ float2 up2(u64 v) {
    float2 f;
    asm("mov.b64 {%0, %1}, %2;" : "=f"(f.x), "=f"(f.y) : "l"(v));
    return f;
}

// ---------------------------------------------------------------------------
// SGEMM: C[M,N] = alpha * A[M,K] @ B[K,N], row-major.
// 128x128 tile, BK=16, 256 threads, 8x8 microtile (acc paired over i).
// Register double-buffered global loads.
// ---------------------------------------------------------------------------
__global__ __launch_bounds__(256) void sgemm128(const float* __restrict__ A,
                                                const float* __restrict__ Bm,
                                                float* __restrict__ C,
                                                int Md, int Nd, int Kd,
                                                float alpha) {
    __shared__ __align__(16) float As[16][128];   // As[k][i]
    __shared__ __align__(16) float Bs[16][128];   // Bs[k][j]

    const int tid = threadIdx.x;
    const int bm = blockIdx.y * 128;
    const int bn = blockIdx.x * 128;
    const int tx = tid & 15;
    const int ty = tid >> 4;

    // A-tile: 128 rows x 16 cols; each thread: 2 float4 (8 cols)
    const int ar = tid >> 1;
    const int ac = (tid & 1) * 8;
    // B-tile: 16 rows x 128 cols; each thread: 2 float4 (8 cols)
    const int br = tid >> 4;
    const int bc = (tid & 15) * 8;

    const float* Ap = A + (size_t)(bm + ar) * Kd + ac;
    const float* Bp = Bm + (size_t)br * Nd + bn + bc;

    u64 acc2[4][8];
#pragma unroll
    for (int i = 0; i < 4; ++i)
#pragma unroll
        for (int j = 0; j < 8; ++j) acc2[i][j] = 0ull;

    // prefetch chunk 0
    float4 a0 = *(const float4*)(Ap);
    float4 a1 = *(const float4*)(Ap + 4);
    float4 b0 = *(const float4*)(Bp);
    float4 b1 = *(const float4*)(Bp + 4);

    for (int k0 = 0; k0 < Kd; k0 += 16) {
        // stage regs -> smem
        As[ac + 0][ar] = a0.x; As[ac + 1][ar] = a0.y;
        As[ac + 2][ar] = a0.z; As[ac + 3][ar] = a0.w;
        As[ac + 4][ar] = a1.x; As[ac + 5][ar] = a1.y;
        As[ac + 6][ar] = a1.z; As[ac + 7][ar] = a1.w;
        *(float4*)&Bs[br][bc] = b0;
        *(float4*)&Bs[br][bc + 4] = b1;
        __syncthreads();

        if (k0 + 16 < Kd) {
            a0 = *(const float4*)(Ap + k0 + 16);
            a1 = *(const float4*)(Ap + k0 + 20);
            b0 = *(const float4*)(Bp + (size_t)(k0 + 16) * Nd);
            b1 = *(const float4*)(Bp + (size_t)(k0 + 16) * Nd + 4);
        }

#pragma unroll
        for (int k = 0; k < 16; ++k) {
            const u64* ap = (const u64*)&As[k][ty * 8];
            u64 pa0 = ap[0], pa1 = ap[1], pa2 = ap[2], pa3 = ap[3];
            float4 bv0 = *(const float4*)&Bs[k][tx * 8];
            float4 bv1 = *(const float4*)&Bs[k][tx * 8 + 4];
            u64 pb[8];
            pb[0] = dup2(bv0.x); pb[1] = dup2(bv0.y);
            pb[2] = dup2(bv0.z); pb[3] = dup2(bv0.w);
            pb[4] = dup2(bv1.x); pb[5] = dup2(bv1.y);
            pb[6] = dup2(bv1.z); pb[7] = dup2(bv1.w);
#pragma unroll
            for (int j = 0; j < 8; ++j) {
                acc2[0][j] = ffma2(pa0, pb[j], acc2[0][j]);
                acc2[1][j] = ffma2(pa1, pb[j], acc2[1][j]);
                acc2[2][j] = ffma2(pa2, pb[j], acc2[2][j]);
                acc2[3][j] = ffma2(pa3, pb[j], acc2[3][j]);
            }
        }
        __syncthreads();
    }

#pragma unroll
    for (int ip = 0; ip < 4; ++ip) {
        float2 c[8];
#pragma unroll
        for (int j = 0; j < 8; ++j) c[j] = up2(acc2[ip][j]);
        float* cp0 = C + (size_t)(bm + ty * 8 + 2 * ip) * Nd + bn + tx * 8;
        float* cp1 = cp0 + Nd;
        *(float4*)cp0 = make_float4(c[0].x * alpha, c[1].x * alpha,
                                    c[2].x * alpha, c[3].x * alpha);
        *(float4*)(cp0 + 4) = make_float4(c[4].x * alpha, c[5].x * alpha,
                                          c[6].x * alpha, c[7].x * alpha);
        *(float4*)cp1 = make_float4(c[0].y * alpha, c[1].y * alpha,
                                    c[2].y * alpha, c[3].y * alpha);
        *(float4*)(cp1 + 4) = make_float4(c[4].y * alpha, c[5].y * alpha,
                                          c[6].y * alpha, c[7].y * alpha);
    }
}

// ---------------------------------------------------------------------------
// relq[bh,i,r] = q[bh,i,:] . rel_k_table[r,:]   (small GEMM 32x129x64 per CTA)
// grid: (L/32, BH); 256 threads = 8(ty: 4 i each) x 32(tx: 4 r each).
// ---------------------------------------------------------------------------
__global__ __launch_bounds__(256) void relq_kernel(const float* __restrict__ relk) {
    __shared__ __align__(16) float qsT[64][36];    // [d][i]  (32 i)
    __shared__ __align__(16) float tsT[64][132];   // [d][r]  (129 r)

    const int tid = threadIdx.x;
    const int bh = blockIdx.y;
    const int b = bh >> 4;
    const int h = bh & 15;
    const int i0 = blockIdx.x * 32;
    const int tx = tid & 31;
    const int ty = tid >> 5;

    // stage q (32 rows x 64 d), transposed
    {
        const int rI = tid >> 3;            // 0..31
        const int seg = (tid & 7) * 8;      // 0..56
        const float* qb = g_q + (size_t)(b * L + i0 + rI) * D + h * DH + seg;
        float4 v0 = *(const float4*)qb;
        float4 v1 = *(const float4*)(qb + 4);
        qsT[seg + 0][rI] = v0.x; qsT[seg + 1][rI] = v0.y;
        qsT[seg + 2][rI] = v0.z; qsT[seg + 3][rI] = v0.w;
        qsT[seg + 4][rI] = v1.x; qsT[seg + 5][rI] = v1.y;
        qsT[seg + 6][rI] = v1.z; qsT[seg + 7][rI] = v1.w;
    }
    // stage table (129 rows x 64 d), transposed
    for (int e = tid; e < R * 64; e += 256) {
        int r = e >> 6, d = e & 63;
        tsT[d][r] = relk[e];
    }
    __syncthreads();

    u64 acc2[2][4];
#pragma unroll
    for (int p = 0; p < 2; ++p)
#pragma unroll
        for (int j = 0; j < 4; ++j) acc2[p][j] = 0ull;

#pragma unroll 8
    for (int d = 0; d < 64; ++d) {
        const u64* ap = (const u64*)&qsT[d][ty * 4];
        u64 pa0 = ap[0], pa1 = ap[1];
        float4 bv = *(const float4*)&tsT[d][tx * 4];
        u64 pb0 = dup2(bv.x), pb1 = dup2(bv.y), pb2 = dup2(bv.z), pb3 = dup2(bv.w);
        acc2[0][0] = ffma2(pa0, pb0, acc2[0][0]);
        acc2[0][1] = ffma2(pa0, pb1, acc2[0][1]);
        acc2[0][2] = ffma2(pa0, pb2, acc2[0][2]);
        acc2[0][3] = ffma2(pa0, pb3, acc2[0][3]);
        acc2[1][0] = ffma2(pa1, pb0, acc2[1][0]);
        acc2[1][1] = ffma2(pa1, pb1, acc2[1][1]);
        acc2[1][2] = ffma2(pa1, pb2, acc2[1][2]);
        acc2[1][3] = ffma2(pa1, pb3, acc2[1][3]);
    }

#pragma unroll
    for (int p = 0; p < 2; ++p) {
        float2 c0 = up2(acc2[p][0]);
        float2 c1 = up2(acc2[p][1]);
        float2 c2 = up2(acc2[p][2]);
        float2 c3 = up2(acc2[p][3]);
        int gi = i0 + ty * 4 + 2 * p;
        float* o0 = g_relq + ((size_t)bh * L + gi) * RP + tx * 4;
        float* o1 = o0 + RP;
        *(float4*)o0 = make_float4(c0.x, c1.x, c2.x, c3.x);
        *(float4*)o1 = make_float4(c0.y, c1.y, c2.y, c3.y);
    }

    // tail: r = 128
    if (tid < 32) {
        float s = 0.0f;
#pragma unroll 8
        for (int d = 0; d < 64; ++d) s += qsT[d][tid] * tsT[d][128];
        g_relq[((size_t)bh * L + i0 + tid) * RP + 128] = s;
    }
}

// ---------------------------------------------------------------------------
// Logits: S[bh,i,j] = q_i . k_j + relq[bh,i,clip(j-i)+64]
// tile 128 i x 32 j, microtile 8 i x 2 j, K=64 staged once.
// grid: (L/32 j, L/128 i, BH); 256 threads.
// ---------------------------------------------------------------------------
__global__ __launch_bounds__(256) void logits_kernel() {
    __shared__ __align__(16) float Qs[64][132];   // [d][i] (128 i)
    __shared__ __align__(16) float Ks[64][36];    // [d][j] (32 j)

    const int tid = threadIdx.x;
    const int bh = blockIdx.z;
    const int b = bh >> 4;
    const int h = bh & 15;
    const int i0 = blockIdx.y * 128;
    const int j0 = blockIdx.x * 32;
    const int tx = tid & 15;
    const int ty = tid >> 4;

    // stage Q (128 rows x 64 d) transposed
    {
        const int rI = tid >> 1;            // 0..127
        const int seg = (tid & 1) * 32;     // 0 or 32
        const float* qb = g_q + (size_t)(b * L + i0 + rI) * D + h * DH + seg;
#pragma unroll
        for (int u = 0; u < 8; ++u) {
            float4 v = *(const float4*)(qb + 4 * u);
            int c = seg + 4 * u;
            Qs[c + 0][rI] = v.x; Qs[c + 1][rI] = v.y;
            Qs[c + 2][rI] = v.z; Qs[c + 3][rI] = v.w;
        }
    }
    // stage K (32 rows x 64 d) transposed
    {
        const int rJ = tid >> 3;            // 0..31
        const int seg = (tid & 7) * 8;      // 0..56
        const float* kb = g_k + (size_t)(b * L + j0 + rJ) * D + h * DH + seg;
        float4 v0 = *(const float4*)kb;
        float4 v1 = *(const float4*)(kb + 4);
        Ks[seg + 0][rJ] = v0.x; Ks[seg + 1][rJ] = v0.y;
        Ks[seg + 2][rJ] = v0.z; Ks[seg + 3][rJ] = v0.w;
        Ks[seg + 4][rJ] = v1.x; Ks[seg + 5][rJ] = v1.y;
        Ks[seg + 6][rJ] = v1.z; Ks[seg + 7][rJ] = v1.w;
    }
    __syncthreads();

    u64 acc2[4][2];
#pragma unroll
    for (int p = 0; p < 4; ++p) { acc2[p][0] = 0ull; acc2[p][1] = 0ull; }

#pragma unroll 8
    for (int d = 0; d < 64; ++d) {
        const u64* ap = (const u64*)&Qs[d][ty * 8];
        u64 pa0 = ap[0], pa1 = ap[1], pa2 = ap[2], pa3 = ap[3];
        float2 bv = *(const float2*)&Ks[d][tx * 2];
        u64 pb0 = dup2(bv.x), pb1 = dup2(bv.y);
        acc2[0][0] = ffma2(pa0, pb0, acc2[0][0]);
        acc2[0][1] = ffma2(pa0, pb1, acc2[0][1]);
        acc2[1][0] = ffma2(pa1, pb0, acc2[1][0]);
        acc2[1][1] = ffma2(pa1, pb1, acc2[1][1]);
        acc2[2][0] = ffma2(pa2, pb0, acc2[2][0]);
        acc2[2][1] = ffma2(pa2, pb1, acc2[2][1]);
        acc2[3][0] = ffma2(pa3, pb0, acc2[3][0]);
        acc2[3][1] = ffma2(pa3, pb1, acc2[3][1]);
    }

    const int gj0 = j0 + tx * 2;
#pragma unroll
    for (int p = 0; p < 4; ++p) {
        float2 c0 = up2(acc2[p][0]);   // (row even, row odd) @ j = gj0
        float2 c1 = up2(acc2[p][1]);   // @ j = gj0+1
        int gi0 = i0 + ty * 8 + 2 * p;
#pragma unroll
        for (int e = 0; e < 2; ++e) {
            int gi = gi0 + e;
            const float* rq = g_relq + ((size_t)bh * L + gi) * RP;
            int r0 = min(max(gj0 + 0 - gi, -MREL), MREL) + MREL;
            int r1 = min(max(gj0 + 1 - gi, -MREL), MREL) + MREL;
            float v0 = (e ? c0.y : c0.x) + rq[r0];
            float v1 = (e ? c1.y : c1.x) + rq[r1];
            *(float2*)(g_s + ((size_t)bh * L + gi) * L + gj0) = make_float2(v0, v1);
        }
    }
}

// ---------------------------------------------------------------------------
// Fused softmax + wsum. One CTA (256 threads) per (bh,i) row.
// ---------------------------------------------------------------------------
__global__ __launch_bounds__(256) void softmax_kernel() {
    __shared__ __align__(16) float sw[L];
    __shared__ float red[256];

    const int row = blockIdx.x;     // bh*L + i
    const int i = row & (L - 1);
    const int tid = threadIdx.x;
    float* srow_g = g_s + (size_t)row * L;

    float4 x4 = *(const float4*)(srow_g + tid * 4);

    float m = fmaxf(fmaxf(x4.x, x4.y), fmaxf(x4.z, x4.w));
    red[tid] = m;
    __syncthreads();
    for (int s = 128; s > 0; s >>= 1) {
        if (tid < s) red[tid] = fmaxf(red[tid], red[tid + s]);
        __syncthreads();
    }
    const float rowmax = red[0];
    __syncthreads();

    x4.x = __expf(x4.x - rowmax);
    x4.y = __expf(x4.y - rowmax);
    x4.z = __expf(x4.z - rowmax);
    x4.w = __expf(x4.w - rowmax);

    red[tid] = x4.x + x4.y + x4.z + x4.w;
    __syncthreads();
    for (int s = 128; s > 0; s >>= 1) {
        if (tid < s) red[tid] += red[tid + s];
        __syncthreads();
    }
    const float inv = 1.0f / red[0];
    __syncthreads();

    x4.x *= inv; x4.y *= inv; x4.z *= inv; x4.w *= inv;
    *(float4*)(sw + tid * 4) = x4;
    *(float4*)(srow_g + tid * 4) = x4;
    __syncthreads();

    const int headEnd = i - MREL;
    const int tailStart = i + MREL;
    float hp = 0.0f, tp = 0.0f;
    for (int j = tid; j <= headEnd; j += 256) hp += sw[j];
    for (int j = tailStart + tid; j < L; j += 256) tp += sw[j];

    red[tid] = hp;
    __syncthreads();
    for (int s = 128; s > 0; s >>= 1) {
        if (tid < s) red[tid] += red[tid + s];
        __syncthreads();
    }
    const float head = red[0];
    __syncthreads();

    red[tid] = tp;
    __syncthreads();
    for (int s = 128; s > 0; s >>= 1) {
        if (tid < s) red[tid] += red[tid + s];
        __syncthreads();
    }
    const float tail = red[0];
    __syncthreads();

    if (tid < R) {
        float val;
        if (tid == 0) {
            val = head;
        } else if (tid == R - 1) {
            val = tail;
        } else {
            int j = i + tid - MREL;
            val = (j >= 0 && j < L) ? sw[j] : 0.0f;
        }
        g_wsum[(size_t)row * RP + tid] = val;
    }
}

// ---------------------------------------------------------------------------
// Attention output: O = W@V + wsum@rel_v_table
// tile 64 i x 64 d, microtile 8 i x 2 d; K=1024 loop in 64-chunks.
// grid: (L/64, BH); 256 threads.
// ---------------------------------------------------------------------------
__global__ __launch_bounds__(256) void attnout_kernel(const float* __restrict__ relv) {
    __shared__ __align__(16) float Ws[64][68];   // [k][i]
    __shared__ __align__(16) float Vs[64][68];   // [k][d]

    const int tid = threadIdx.x;
    const int bh = blockIdx.y;
    const int b = bh >> 4;
    const int h = bh & 15;
    const int i0 = blockIdx.x * 64;
    const int tx = tid & 31;     // d pair index
    const int ty = tid >> 5;     // i group (8 rows)

    const int rI = tid >> 2;
    const int seg = (tid & 3) * 16;

    u64 acc2[4][2];
#pragma unroll
    for (int p = 0; p < 4; ++p) { acc2[p][0] = 0ull; acc2[p][1] = 0ull; }

    for (int k0 = 0; k0 < L; k0 += 64) {
        // stage W (rows i0.., cols k0..) transposed -> Ws[k][i]
        const float* wb = g_s + ((size_t)bh * L + i0 + rI) * L + k0 + seg;
#pragma unroll
        for (int u = 0; u < 4; ++u) {
            float4 v = *(const float4*)(wb + 4 * u);
            int c = seg + 4 * u;
            Ws[c + 0][rI] = v.x; Ws[c + 1][rI] = v.y;
            Ws[c + 2][rI] = v.z; Ws[c + 3][rI] = v.w;
        }
        // stage V natural: Vs[k][d]
        const float* vb = g_v + (size_t)(b * L + k0 + rI) * D + h * DH + seg;
#pragma unroll
        for (int u = 0; u < 4; ++u)
            *(float4*)&Vs[rI][seg + 4 * u] = *(const float4*)(vb + 4 * u);
        __syncthreads();

#pragma unroll 8
        for (int k = 0; k < 64; ++k) {
            const u64* ap = (const u64*)&Ws[k][ty * 8];
            u64 pa0 = ap[0], pa1 = ap[1], pa2 = ap[2], pa3 = ap[3];
            float2 bv = *(const float2*)&Vs[k][tx * 2];
            u64 pb0 = dup2(bv.x), pb1 = dup2(bv.y);
            acc2[0][0] = ffma2(pa0, pb0, acc2[0][0]);
            acc2[0][1] = ffma2(pa0, pb1, acc2[0][1]);
            acc2[1][0] = ffma2(pa1, pb0, acc2[1][0]);
            acc2[1][1] = ffma2(pa1, pb1, acc2[1][1]);
            acc2[2][0] = ffma2(pa2, pb0, acc2[2][0]);
            acc2[2][1] = ffma2(pa2, pb1, acc2[2][1]);
            acc2[3][0] = ffma2(pa3, pb0, acc2[3][0]);
            acc2[3][1] = ffma2(pa3, pb1, acc2[3][1]);
        }
        __syncthreads();
    }

    // rel_v epilogue: acc[i][d] += wsum[i][r] * relv[r][d]
    const float* wsbase = g_wsum + ((size_t)bh * L + i0 + ty * 8) * RP;
    for (int r = 0; r < R; ++r) {
        float2 tv = __ldg((const float2*)(relv + r * DH + tx * 2));
        u64 pt0 = dup2(tv.x), pt1 = dup2(tv.y);
#pragma unroll
        for (int p = 0; p < 4; ++p) {
            float w0 = __ldg(wsbase + (size_t)(2 * p) * RP + r);
            float w1 = __ldg(wsbase + (size_t)(2 * p + 1) * RP + r);
            u64 pw = pk2(w0, w1);
            acc2[p][0] = ffma2(pw, pt0, acc2[p][0]);
            acc2[p][1] = ffma2(pw, pt1, acc2[p][1]);
        }
    }

#pragma unroll
    for (int p = 0; p < 4; ++p) {
        float2 c0 = up2(acc2[p][0]);   // (row even, row odd) @ d = tx*2
        float2 c1 = up2(acc2[p][1]);   // @ d = tx*2+1
        int gi = i0 + ty * 8 + 2 * p;
        float* o0 = g_o + (size_t)(b * L + gi) * D + h * DH + tx * 2;
        float* o1 = o0 + D;
        *(float2*)o0 = make_float2(c0.x, c1.x);
        *(float2*)o1 = make_float2(c0.y, c1.y);
    }
}

// ---------------------------------------------------------------------------
// Launch
// ---------------------------------------------------------------------------
extern "C" void kernel_launch(void* const* d_in, const int* in_sizes, int n_in,
                              void* d_out, int out_size) {
    const float* x    = (const float*)d_in[0];
    const float* Wq   = (const float*)d_in[1];
    const float* Wk   = (const float*)d_in[2];
    const float* Wv   = (const float*)d_in[3];
    const float* Wo   = (const float*)d_in[4];
    const float* relk = (const float*)d_in[5];
    const float* relv = (const float*)d_in[6];
    float* out = (float*)d_out;

    float *pq, *pk, *pv, *po;
    cudaGetSymbolAddress((void**)&pq, g_q);
    cudaGetSymbolAddress((void**)&pk, g_k);
    cudaGetSymbolAddress((void**)&pv, g_v);
    cudaGetSymbolAddress((void**)&po, g_o);

    const dim3 gg(D / 128, NT / 128);   // (8, 16)
    const float qscale = 0.125f;        // DH^-0.5

    sgemm128<<<gg, 256>>>(x, Wq, pq, NT, D, D, qscale);
    sgemm128<<<gg, 256>>>(x, Wk, pk, NT, D, D, 1.0f);
    sgemm128<<<gg, 256>>>(x, Wv, pv, NT, D, D, 1.0f);

    relq_kernel<<<dim3(L / 32, BH), 256>>>(relk);

    logits_kernel<<<dim3(L / 32, L / 128, BH), 256>>>();

    softmax_kernel<<<BH * L, 256>>>();

    attnout_kernel<<<dim3(L / 64, BH), 256>>>(relv);

    sgemm128<<<gg, 256>>>(po, Wo, out, NT, D, D, 1.0f);
}

// round 6
// speedup vs baseline: 1.4863x; 1.2245x over previous
#include <cuda_runtime.h>
#include <cuda_bf16.h>

// ---------------------------------------------------------------------------
// MultiHead2DAttention (Shaw relative positions, T2T variant)
// B=2, L=1024, D=1024, H=16, DH=64, M=64, R=129
// Round 5: the four 2048x1024x1024 projection/output GEMMs move to tensor
// cores (mma.sync bf16 m16n8k16) with a 3-term error-compensated bf16 split
// (hi*hi + hi*lo + lo*hi, fp32 accumulate) -> ~1e-5 relative accuracy.
// Attention-side kernels unchanged from round 4.
// ---------------------------------------------------------------------------

namespace {
constexpr int B  = 2;
constexpr int L  = 1024;
constexpr int D  = 1024;
constexpr int H  = 16;
constexpr int DH = 64;
constexpr int MREL = 64;
constexpr int R  = 2 * MREL + 1;   // 129
constexpr int RP = 132;            // padded row stride for relq/wsum
constexpr int NT = B * L;          // 2048
constexpr int BH = B * H;          // 32
}

typedef __nv_bfloat16 bf16;
typedef unsigned long long u64;
typedef unsigned int u32;

// Scratch buffers (device globals: no allocations allowed)
__device__ float g_q[NT * D];
__device__ float g_k[NT * D];
__device__ float g_v[NT * D];
__device__ float g_o[NT * D];
__device__ float g_relq[(size_t)BH * L * RP];
__device__ float g_s[(size_t)BH * L * L];      // 128 MB
__device__ float g_wsum[(size_t)BH * L * RP];

// bf16 split buffers
__device__ bf16 g_xh[NT * D];
__device__ bf16 g_xl[NT * D];
__device__ bf16 g_wh[D * D];     // transposed [N][K]
__device__ bf16 g_wl[D * D];

// ---------------------------------------------------------------------------
// packed fp32 helpers (round-4 kernels)
// ---------------------------------------------------------------------------
__device__ __forceinline__ u64 pk2(float x, float y) {
    u64 r;
    asm("mov.b64 %0, {%1, %2};" : "=l"(r) : "f"(x), "f"(y));
    return r;
}
__device__ __forceinline__ u64 dup2(float x) { return pk2(x, x); }
__device__ __forceinline__ u64 ffma2(u64 a, u64 b, u64 c) {
    u64 d;
    asm("fma.rn.f32x2 %0, %1, %2, %3;" : "=l"(d) : "l"(a), "l"(b), "l"(c));
    return d;
}
__device__ __forceinline__ float2 up2(u64 v) {
    float2 f;
    asm("mov.b64 {%0, %1}, %2;" : "=f"(f.x), "=f"(f.y) : "l"(v));
    return f;
}

// ---------------------------------------------------------------------------
// mma helper: D(f32) += A(bf16 16x16) * B(bf16 16x8)
// ---------------------------------------------------------------------------
__device__ __forceinline__ void mma16816(float* c, const u32* a, const u32* b) {
    asm volatile(
        "mma.sync.aligned.m16n8k16.row.col.f32.bf16.bf16.f32 "
        "{%0,%1,%2,%3},{%4,%5,%6,%7},{%8,%9},{%0,%1,%2,%3};"
        : "+f"(c[0]), "+f"(c[1]), "+f"(c[2]), "+f"(c[3])
        : "r"(a[0]), "r"(a[1]), "r"(a[2]), "r"(a[3]), "r"(b[0]), "r"(b[1]));
}

__device__ __forceinline__ void cp16(u32 smem_addr, const void* gptr) {
    asm volatile("cp.async.cg.shared.global [%0], [%1], 16;"
                 :: "r"(smem_addr), "l"(gptr));
}

// ---------------------------------------------------------------------------
// split: src fp32 -> hi/lo bf16 (elementwise), n = grid*256*4 elements
// ---------------------------------------------------------------------------
__global__ __launch_bounds__(256) void split_kernel(const float* __restrict__ src,
                                                    bf16* __restrict__ hi,
                                                    bf16* __restrict__ lo) {
    int i = (blockIdx.x * 256 + threadIdx.x) * 4;
    float4 v = *(const float4*)(src + i);
    bf16 h0 = __float2bfloat16(v.x);
    bf16 h1 = __float2bfloat16(v.y);
    bf16 h2 = __float2bfloat16(v.z);
    bf16 h3 = __float2bfloat16(v.w);
    bf16 l0 = __float2bfloat16(v.x - __bfloat162float(h0));
    bf16 l1 = __float2bfloat16(v.y - __bfloat162float(h1));
    bf16 l2 = __float2bfloat16(v.z - __bfloat162float(h2));
    bf16 l3 = __float2bfloat16(v.w - __bfloat162float(h3));
    __nv_bfloat162* hp = (__nv_bfloat162*)(hi + i);
    __nv_bfloat162* lp = (__nv_bfloat162*)(lo + i);
    hp[0] = __nv_bfloat162(h0, h1);
    hp[1] = __nv_bfloat162(h2, h3);
    lp[0] = __nv_bfloat162(l0, l1);
    lp[1] = __nv_bfloat162(l2, l3);
}

// ---------------------------------------------------------------------------
// splitT: W[K][N] fp32 -> transposed hi/lo bf16 [N][K]
// grid (32,32), block (32,8)
// ---------------------------------------------------------------------------
__global__ void splitT_kernel(const float* __restrict__ W,
                              bf16* __restrict__ th, bf16* __restrict__ tl) {
    __shared__ float ts[32][33];
    const int tx = threadIdx.x, ty = threadIdx.y;
    const int n0 = blockIdx.x * 32, k0 = blockIdx.y * 32;
    for (int r = ty; r < 32; r += 8)
        ts[r][tx] = W[(size_t)(k0 + r) * D + n0 + tx];
    __syncthreads();
    for (int r = ty; r < 32; r += 8) {
        float v = ts[tx][r];
        bf16 h = __float2bfloat16(v);
        bf16 l = __float2bfloat16(v - __bfloat162float(h));
        th[(size_t)(n0 + r) * D + k0 + tx] = h;
        tl[(size_t)(n0 + r) * D + k0 + tx] = l;
    }
}

// ---------------------------------------------------------------------------
// hgemm3x: C[M,N] = alpha * A[M,K] @ B[K,N]  (A given as hi/lo bf16 row-major,
// B given as hi/lo bf16 TRANSPOSED [N][K]).  3-pass compensated bf16 MMA.
// CTA tile 128x128, BK=16, 8 warps (warp tile 64x32), double-buffered cp.async.
// ---------------------------------------------------------------------------
__global__ __launch_bounds__(256) void hgemm3x(const bf16* __restrict__ Ah,
                                               const bf16* __restrict__ Al,
                                               const bf16* __restrict__ Bh,
                                               const bf16* __restrict__ Bl,
                                               float* __restrict__ C,
                                               int Md, int Nd, int Kd,
                                               float alpha) {
    constexpr int STR = 24;            // smem row stride (bf16) -> conflict-free
    constexpr int STG = 128 * STR;     // elements per stage per array
    __shared__ bf16 As_h[2 * STG];
    __shared__ bf16 As_l[2 * STG];
    __shared__ bf16 Bs_h[2 * STG];
    __shared__ bf16 Bs_l[2 * STG];

    const int tid = threadIdx.x;
    const int bm = blockIdx.y * 128;
    const int bn = blockIdx.x * 128;
    const int wid = tid >> 5;
    const int lane = tid & 31;
    const int g = lane >> 2;
    const int tg = lane & 3;
    const int wm = (wid & 1) * 64;
    const int wn = (wid >> 1) * 32;

    // cp.async mapping: each thread moves one 16B chunk per array per tile
    const int lrow = tid >> 1;            // 0..127
    const int lseg = (tid & 1) * 8;       // 0 or 8 (bf16)
    const size_t aoff = (size_t)(bm + lrow) * Kd + lseg;
    const size_t boff = (size_t)(bn + lrow) * Kd + lseg;
    const u32 sdst = (u32)(lrow * STR + lseg) * 2;   // byte offset in stage
    const u32 s_ah = (u32)__cvta_generic_to_shared(As_h);
    const u32 s_al = (u32)__cvta_generic_to_shared(As_l);
    const u32 s_bh = (u32)__cvta_generic_to_shared(Bs_h);
    const u32 s_bl = (u32)__cvta_generic_to_shared(Bs_l);

    float acc[4][4][4];
#pragma unroll
    for (int ma = 0; ma < 4; ++ma)
#pragma unroll
        for (int na = 0; na < 4; ++na)
#pragma unroll
            for (int e = 0; e < 4; ++e) acc[ma][na][e] = 0.0f;

    const int nT = Kd / 16;

    // prologue: stage 0
    {
        const u32 o = sdst;
        cp16(s_ah + o, Ah + aoff);
        cp16(s_al + o, Al + aoff);
        cp16(s_bh + o, Bh + boff);
        cp16(s_bl + o, Bl + boff);
        asm volatile("cp.async.commit_group;");
    }

    for (int kt = 0; kt < nT; ++kt) {
        const int stg = kt & 1;
        if (kt + 1 < nT) {
            const u32 o = (u32)((stg ^ 1) * STG * 2) + sdst;
            const size_t ko = (size_t)(kt + 1) * 16;
            cp16(s_ah + o, Ah + aoff + ko);
            cp16(s_al + o, Al + aoff + ko);
            cp16(s_bh + o, Bh + boff + ko);
            cp16(s_bl + o, Bl + boff + ko);
            asm volatile("cp.async.commit_group;");
            asm volatile("cp.async.wait_group 1;");
        } else {
            asm volatile("cp.async.wait_group 0;");
        }
        __syncthreads();

        const bf16* Abh = As_h + stg * STG;
        const bf16* Abl = As_l + stg * STG;
        const bf16* Bbh = Bs_h + stg * STG;
        const bf16* Bbl = Bs_l + stg * STG;

        u32 ah[4][4], al[4][4], bh[4][2], bl[4][2];
#pragma unroll
        for (int ma = 0; ma < 4; ++ma) {
            const int r0 = (wm + ma * 16 + g) * STR + 2 * tg;
            const int r1 = r0 + 8 * STR;
            ah[ma][0] = *(const u32*)(Abh + r0);
            ah[ma][1] = *(const u32*)(Abh + r1);
            ah[ma][2] = *(const u32*)(Abh + r0 + 8);
            ah[ma][3] = *(const u32*)(Abh + r1 + 8);
            al[ma][0] = *(const u32*)(Abl + r0);
            al[ma][1] = *(const u32*)(Abl + r1);
            al[ma][2] = *(const u32*)(Abl + r0 + 8);
            al[ma][3] = *(const u32*)(Abl + r1 + 8);
        }
#pragma unroll
        for (int na = 0; na < 4; ++na) {
            const int c0 = (wn + na * 8 + g) * STR + 2 * tg;
            bh[na][0] = *(const u32*)(Bbh + c0);
            bh[na][1] = *(const u32*)(Bbh + c0 + 8);
            bl[na][0] = *(const u32*)(Bbl + c0);
            bl[na][1] = *(const u32*)(Bbl + c0 + 8);
        }

        // pass-major ordering: same accumulator revisited at distance 16
#pragma unroll
        for (int ma = 0; ma < 4; ++ma)
#pragma unroll
            for (int na = 0; na < 4; ++na)
                mma16816(acc[ma][na], ah[ma], bh[na]);
#pragma unroll
        for (int ma = 0; ma < 4; ++ma)
#pragma unroll
            for (int na = 0; na < 4; ++na)
                mma16816(acc[ma][na], ah[ma], bl[na]);
#pragma unroll
        for (int ma = 0; ma < 4; ++ma)
#pragma unroll
            for (int na = 0; na < 4; ++na)
                mma16816(acc[ma][na], al[ma], bh[na]);
        __syncthreads();
    }

    // writeout
#pragma unroll
    for (int ma = 0; ma < 4; ++ma) {
#pragma unroll
        for (int na = 0; na < 4; ++na) {
            const int r0 = bm + wm + ma * 16 + g;
            const int c = bn + wn + na * 8 + 2 * tg;
            *(float2*)(C + (size_t)r0 * Nd + c) =
                make_float2(acc[ma][na][0] * alpha, acc[ma][na][1] * alpha);
            *(float2*)(C + (size_t)(r0 + 8) * Nd + c) =
                make_float2(acc[ma][na][2] * alpha, acc[ma][na][3] * alpha);
        }
    }
}

// ---------------------------------------------------------------------------
// relq[bh,i,r] = q[bh,i,:] . rel_k_table[r,:]
// ---------------------------------------------------------------------------
__global__ __launch_bounds__(256) void relq_kernel(const float* __restrict__ relk) {
    __shared__ __align__(16) float qsT[64][36];
    __shared__ __align__(16) float tsT[64][132];

    const int tid = threadIdx.x;
    const int bh = blockIdx.y;
    const int b = bh >> 4;
    const int h = bh & 15;
    const int i0 = blockIdx.x * 32;
    const int tx = tid & 31;
    const int ty = tid >> 5;

    {
        const int rI = tid >> 3;
        const int seg = (tid & 7) * 8;
        const float* qb = g_q + (size_t)(b * L + i0 + rI) * D + h * DH + seg;
        float4 v0 = *(const float4*)qb;
        float4 v1 = *(const float4*)(qb + 4);
        qsT[seg + 0][rI] = v0.x; qsT[seg + 1][rI] = v0.y;
        qsT[seg + 2][rI] = v0.z; qsT[seg + 3][rI] = v0.w;
        qsT[seg + 4][rI] = v1.x; qsT[seg + 5][rI] = v1.y;
        qsT[seg + 6][rI] = v1.z; qsT[seg + 7][rI] = v1.w;
    }
    for (int e = tid; e < R * 64; e += 256) {
        int r = e >> 6, d = e & 63;
        tsT[d][r] = relk[e];
    }
    __syncthreads();

    u64 acc2[2][4];
#pragma unroll
    for (int p = 0; p < 2; ++p)
#pragma unroll
        for (int j = 0; j < 4; ++j) acc2[p][j] = 0ull;

#pragma unroll 8
    for (int d = 0; d < 64; ++d) {
        const u64* ap = (const u64*)&qsT[d][ty * 4];
        u64 pa0 = ap[0], pa1 = ap[1];
        float4 bv = *(const float4*)&tsT[d][tx * 4];
        u64 pb0 = dup2(bv.x), pb1 = dup2(bv.y), pb2 = dup2(bv.z), pb3 = dup2(bv.w);
        acc2[0][0] = ffma2(pa0, pb0, acc2[0][0]);
        acc2[0][1] = ffma2(pa0, pb1, acc2[0][1]);
        acc2[0][2] = ffma2(pa0, pb2, acc2[0][2]);
        acc2[0][3] = ffma2(pa0, pb3, acc2[0][3]);
        acc2[1][0] = ffma2(pa1, pb0, acc2[1][0]);
        acc2[1][1] = ffma2(pa1, pb1, acc2[1][1]);
        acc2[1][2] = ffma2(pa1, pb2, acc2[1][2]);
        acc2[1][3] = ffma2(pa1, pb3, acc2[1][3]);
    }

#pragma unroll
    for (int p = 0; p < 2; ++p) {
        float2 c0 = up2(acc2[p][0]);
        float2 c1 = up2(acc2[p][1]);
        float2 c2 = up2(acc2[p][2]);
        float2 c3 = up2(acc2[p][3]);
        int gi = i0 + ty * 4 + 2 * p;
        float* o0 = g_relq + ((size_t)bh * L + gi) * RP + tx * 4;
        float* o1 = o0 + RP;
        *(float4*)o0 = make_float4(c0.x, c1.x, c2.x, c3.x);
        *(float4*)o1 = make_float4(c0.y, c1.y, c2.y, c3.y);
    }

    if (tid < 32) {
        float s = 0.0f;
#pragma unroll 8
        for (int d = 0; d < 64; ++d) s += qsT[d][tid] * tsT[d][128];
        g_relq[((size_t)bh * L + i0 + tid) * RP + 128] = s;
    }
}

// ---------------------------------------------------------------------------
// Logits: S[bh,i,j] = q_i . k_j + relq[bh,i,clip(j-i)+64]
// ---------------------------------------------------------------------------
__global__ __launch_bounds__(256) void logits_kernel() {
    __shared__ __align__(16) float Qs[64][132];
    __shared__ __align__(16) float Ks[64][36];

    const int tid = threadIdx.x;
    const int bh = blockIdx.z;
    const int b = bh >> 4;
    const int h = bh & 15;
    const int i0 = blockIdx.y * 128;
    const int j0 = blockIdx.x * 32;
    const int tx = tid & 15;
    const int ty = tid >> 4;

    {
        const int rI = tid >> 1;
        const int seg = (tid & 1) * 32;
        const float* qb = g_q + (size_t)(b * L + i0 + rI) * D + h * DH + seg;
#pragma unroll
        for (int u = 0; u < 8; ++u) {
            float4 v = *(const float4*)(qb + 4 * u);
            int c = seg + 4 * u;
            Qs[c + 0][rI] = v.x; Qs[c + 1][rI] = v.y;
            Qs[c + 2][rI] = v.z; Qs[c + 3][rI] = v.w;
        }
    }
    {
        const int rJ = tid >> 3;
        const int seg = (tid & 7) * 8;
        const float* kb = g_k + (size_t)(b * L + j0 + rJ) * D + h * DH + seg;
        float4 v0 = *(const float4*)kb;
        float4 v1 = *(const float4*)(kb + 4);
        Ks[seg + 0][rJ] = v0.x; Ks[seg + 1][rJ] = v0.y;
        Ks[seg + 2][rJ] = v0.z; Ks[seg + 3][rJ] = v0.w;
        Ks[seg + 4][rJ] = v1.x; Ks[seg + 5][rJ] = v1.y;
        Ks[seg + 6][rJ] = v1.z; Ks[seg + 7][rJ] = v1.w;
    }
    __syncthreads();

    u64 acc2[4][2];
#pragma unroll
    for (int p = 0; p < 4; ++p) { acc2[p][0] = 0ull; acc2[p][1] = 0ull; }

#pragma unroll 8
    for (int d = 0; d < 64; ++d) {
        const u64* ap = (const u64*)&Qs[d][ty * 8];
        u64 pa0 = ap[0], pa1 = ap[1], pa2 = ap[2], pa3 = ap[3];
        float2 bv = *(const float2*)&Ks[d][tx * 2];
        u64 pb0 = dup2(bv.x), pb1 = dup2(bv.y);
        acc2[0][0] = ffma2(pa0, pb0, acc2[0][0]);
        acc2[0][1] = ffma2(pa0, pb1, acc2[0][1]);
        acc2[1][0] = ffma2(pa1, pb0, acc2[1][0]);
        acc2[1][1] = ffma2(pa1, pb1, acc2[1][1]);
        acc2[2][0] = ffma2(pa2, pb0, acc2[2][0]);
        acc2[2][1] = ffma2(pa2, pb1, acc2[2][1]);
        acc2[3][0] = ffma2(pa3, pb0, acc2[3][0]);
        acc2[3][1] = ffma2(pa3, pb1, acc2[3][1]);
    }

    const int gj0 = j0 + tx * 2;
#pragma unroll
    for (int p = 0; p < 4; ++p) {
        float2 c0 = up2(acc2[p][0]);
        float2 c1 = up2(acc2[p][1]);
        int gi0 = i0 + ty * 8 + 2 * p;
#pragma unroll
        for (int e = 0; e < 2; ++e) {
            int gi = gi0 + e;
            const float* rq = g_relq + ((size_t)bh * L + gi) * RP;
            int r0 = min(max(gj0 + 0 - gi, -MREL), MREL) + MREL;
            int r1 = min(max(gj0 + 1 - gi, -MREL), MREL) + MREL;
            float v0 = (e ? c0.y : c0.x) + rq[r0];
            float v1 = (e ? c1.y : c1.x) + rq[r1];
            *(float2*)(g_s + ((size_t)bh * L + gi) * L + gj0) = make_float2(v0, v1);
        }
    }
}

// ---------------------------------------------------------------------------
// Fused softmax + wsum. One CTA (256 threads) per (bh,i) row.
// ---------------------------------------------------------------------------
__global__ __launch_bounds__(256) void softmax_kernel() {
    __shared__ __align__(16) float sw[L];
    __shared__ float red[256];

    const int row = blockIdx.x;
    const int i = row & (L - 1);
    const int tid = threadIdx.x;
    float* srow_g = g_s + (size_t)row * L;

    float4 x4 = *(const float4*)(srow_g + tid * 4);

    float m = fmaxf(fmaxf(x4.x, x4.y), fmaxf(x4.z, x4.w));
    red[tid] = m;
    __syncthreads();
    for (int s = 128; s > 0; s >>= 1) {
        if (tid < s) red[tid] = fmaxf(red[tid], red[tid + s]);
        __syncthreads();
    }
    const float rowmax = red[0];
    __syncthreads();

    x4.x = __expf(x4.x - rowmax);
    x4.y = __expf(x4.y - rowmax);
    x4.z = __expf(x4.z - rowmax);
    x4.w = __expf(x4.w - rowmax);

    red[tid] = x4.x + x4.y + x4.z + x4.w;
    __syncthreads();
    for (int s = 128; s > 0; s >>= 1) {
        if (tid < s) red[tid] += red[tid + s];
        __syncthreads();
    }
    const float inv = 1.0f / red[0];
    __syncthreads();

    x4.x *= inv; x4.y *= inv; x4.z *= inv; x4.w *= inv;
    *(float4*)(sw + tid * 4) = x4;
    *(float4*)(srow_g + tid * 4) = x4;
    __syncthreads();

    const int headEnd = i - MREL;
    const int tailStart = i + MREL;
    float hp = 0.0f, tp = 0.0f;
    for (int j = tid; j <= headEnd; j += 256) hp += sw[j];
    for (int j = tailStart + tid; j < L; j += 256) tp += sw[j];

    red[tid] = hp;
    __syncthreads();
    for (int s = 128; s > 0; s >>= 1) {
        if (tid < s) red[tid] += red[tid + s];
        __syncthreads();
    }
    const float head = red[0];
    __syncthreads();

    red[tid] = tp;
    __syncthreads();
    for (int s = 128; s > 0; s >>= 1) {
        if (tid < s) red[tid] += red[tid + s];
        __syncthreads();
    }
    const float tail = red[0];
    __syncthreads();

    if (tid < R) {
        float val;
        if (tid == 0) {
            val = head;
        } else if (tid == R - 1) {
            val = tail;
        } else {
            int j = i + tid - MREL;
            val = (j >= 0 && j < L) ? sw[j] : 0.0f;
        }
        g_wsum[(size_t)row * RP + tid] = val;
    }
}

// ---------------------------------------------------------------------------
// Attention output: O = W@V + wsum@rel_v_table
// ---------------------------------------------------------------------------
__global__ __launch_bounds__(256) void attnout_kernel(const float* __restrict__ relv) {
    __shared__ __align__(16) float Ws[64][68];
    __shared__ __align__(16) float Vs[64][68];

    const int tid = threadIdx.x;
    const int bh = blockIdx.y;
    const int b = bh >> 4;
    const int h = bh & 15;
    const int i0 = blockIdx.x * 64;
    const int tx = tid & 31;
    const int ty = tid >> 5;

    const int rI = tid >> 2;
    const int seg = (tid & 3) * 16;

    u64 acc2[4][2];
#pragma unroll
    for (int p = 0; p < 4; ++p) { acc2[p][0] = 0ull; acc2[p][1] = 0ull; }

    for (int k0 = 0; k0 < L; k0 += 64) {
        const float* wb = g_s + ((size_t)bh * L + i0 + rI) * L + k0 + seg;
#pragma unroll
        for (int u = 0; u < 4; ++u) {
            float4 v = *(const float4*)(wb + 4 * u);
            int c = seg + 4 * u;
            Ws[c + 0][rI] = v.x; Ws[c + 1][rI] = v.y;
            Ws[c + 2][rI] = v.z; Ws[c + 3][rI] = v.w;
        }
        const float* vb = g_v + (size_t)(b * L + k0 + rI) * D + h * DH + seg;
#pragma unroll
        for (int u = 0; u < 4; ++u)
            *(float4*)&Vs[rI][seg + 4 * u] = *(const float4*)(vb + 4 * u);
        __syncthreads();

#pragma unroll 8
        for (int k = 0; k < 64; ++k) {
            const u64* ap = (const u64*)&Ws[k][ty * 8];
            u64 pa0 = ap[0], pa1 = ap[1], pa2 = ap[2], pa3 = ap[3];
            float2 bv = *(const float2*)&Vs[k][tx * 2];
            u64 pb0 = dup2(bv.x), pb1 = dup2(bv.y);
            acc2[0][0] = ffma2(pa0, pb0, acc2[0][0]);
            acc2[0][1] = ffma2(pa0, pb1, acc2[0][1]);
            acc2[1][0] = ffma2(pa1, pb0, acc2[1][0]);
            acc2[1][1] = ffma2(pa1, pb1, acc2[1][1]);
            acc2[2][0] = ffma2(pa2, pb0, acc2[2][0]);
            acc2[2][1] = ffma2(pa2, pb1, acc2[2][1]);
            acc2[3][0] = ffma2(pa3, pb0, acc2[3][0]);
            acc2[3][1] = ffma2(pa3, pb1, acc2[3][1]);
        }
        __syncthreads();
    }

    const float* wsbase = g_wsum + ((size_t)bh * L + i0 + ty * 8) * RP;
    for (int r = 0; r < R; ++r) {
        float2 tv = __ldg((const float2*)(relv + r * DH + tx * 2));
        u64 pt0 = dup2(tv.x), pt1 = dup2(tv.y);
#pragma unroll
        for (int p = 0; p < 4; ++p) {
            float w0 = __ldg(wsbase + (size_t)(2 * p) * RP + r);
            float w1 = __ldg(wsbase + (size_t)(2 * p + 1) * RP + r);
            u64 pw = pk2(w0, w1);
            acc2[p][0] = ffma2(pw, pt0, acc2[p][0]);
            acc2[p][1] = ffma2(pw, pt1, acc2[p][1]);
        }
    }

#pragma unroll
    for (int p = 0; p < 4; ++p) {
        float2 c0 = up2(acc2[p][0]);
        float2 c1 = up2(acc2[p][1]);
        int gi = i0 + ty * 8 + 2 * p;
        float* o0 = g_o + (size_t)(b * L + gi) * D + h * DH + tx * 2;
        float* o1 = o0 + D;
        *(float2*)o0 = make_float2(c0.x, c1.x);
        *(float2*)o1 = make_float2(c0.y, c1.y);
    }
}

// ---------------------------------------------------------------------------
// Launch
// ---------------------------------------------------------------------------
extern "C" void kernel_launch(void* const* d_in, const int* in_sizes, int n_in,
                              void* d_out, int out_size) {
    const float* x    = (const float*)d_in[0];
    const float* Wq   = (const float*)d_in[1];
    const float* Wk   = (const float*)d_in[2];
    const float* Wv   = (const float*)d_in[3];
    const float* Wo   = (const float*)d_in[4];
    const float* relk = (const float*)d_in[5];
    const float* relv = (const float*)d_in[6];
    float* out = (float*)d_out;

    float *pq, *pk, *pv, *po;
    cudaGetSymbolAddress((void**)&pq, g_q);
    cudaGetSymbolAddress((void**)&pk, g_k);
    cudaGetSymbolAddress((void**)&pv, g_v);
    cudaGetSymbolAddress((void**)&po, g_o);
    bf16 *xh, *xl, *wh, *wl;
    cudaGetSymbolAddress((void**)&xh, g_xh);
    cudaGetSymbolAddress((void**)&xl, g_xl);
    cudaGetSymbolAddress((void**)&wh, g_wh);
    cudaGetSymbolAddress((void**)&wl, g_wl);

    const dim3 gg(D / 128, NT / 128);       // (8, 16) = 128 CTAs
    const dim3 gt(32, 32);
    const dim3 bt(32, 8);
    const int splitBlocks = (NT * D) / (256 * 4);   // 2048
    const float qscale = 0.125f;            // DH^-0.5

    // x split once, reused for q/k/v
    split_kernel<<<splitBlocks, 256>>>(x, xh, xl);

    splitT_kernel<<<gt, bt>>>(Wq, wh, wl);
    hgemm3x<<<gg, 256>>>(xh, xl, wh, wl, pq, NT, D, D, qscale);

    splitT_kernel<<<gt, bt>>>(Wk, wh, wl);
    hgemm3x<<<gg, 256>>>(xh, xl, wh, wl, pk, NT, D, D, 1.0f);

    splitT_kernel<<<gt, bt>>>(Wv, wh, wl);
    hgemm3x<<<gg, 256>>>(xh, xl, wh, wl, pv, NT, D, D, 1.0f);

    relq_kernel<<<dim3(L / 32, BH), 256>>>(relk);
    logits_kernel<<<dim3(L / 32, L / 128, BH), 256>>>();
    softmax_kernel<<<BH * L, 256>>>();
    attnout_kernel<<<dim3(L / 64, BH), 256>>>(relv);

    // final projection: split o (reuses x split buffers), then GEMM
    split_kernel<<<splitBlocks, 256>>>(po, xh, xl);
    splitT_kernel<<<gt, bt>>>(Wo, wh, wl);
    hgemm3x<<<gg, 256>>>(xh, xl, wh, wl, out, NT, D, D, 1.0f);
}

// round 8
// speedup vs baseline: 1.5700x; 1.0563x over previous
#include <cuda_runtime.h>
#include <cuda_bf16.h>
#include <cstdint>

// ---------------------------------------------------------------------------
// MultiHead2DAttention (Shaw relative positions, T2T variant)
// B=2, L=1024, D=1024, H=16, DH=64, M=64, R=129
// Round 7: tcgen05 unavailable (harness compiles virtual arch compute_100).
// Keep R5 mma.sync compensated-bf16 GEMMs; NEW: fused logits+softmax+wsum
// kernel (full score rows in smem) removing 256MB of S round-trips and one
// kernel launch.
// ---------------------------------------------------------------------------

namespace {
constexpr int B  = 2;
constexpr int L  = 1024;
constexpr int D  = 1024;
constexpr int H  = 16;
constexpr int DH = 64;
constexpr int MREL = 64;
constexpr int R  = 2 * MREL + 1;   // 129
constexpr int RP = 132;            // padded row stride for relq/wsum
constexpr int NT = B * L;          // 2048
constexpr int BH = B * H;          // 32
}

typedef __nv_bfloat16 bf16;
typedef unsigned long long u64;
typedef unsigned int u32;

// Scratch buffers (device globals: no allocations allowed)
__device__ float g_q[NT * D];
__device__ float g_k[NT * D];
__device__ float g_v[NT * D];
__device__ float g_o[NT * D];
__device__ float g_relq[(size_t)BH * L * RP];
__device__ float g_s[(size_t)BH * L * L];      // 128 MB (softmax weights)
__device__ float g_wsum[(size_t)BH * L * RP];

// bf16 split buffers
__device__ bf16 g_xh[NT * D];
__device__ bf16 g_xl[NT * D];
__device__ bf16 g_wh[D * D];     // transposed [N][K]
__device__ bf16 g_wl[D * D];

// ---------------------------------------------------------------------------
// packed fp32 helpers
// ---------------------------------------------------------------------------
__device__ __forceinline__ u64 pk2(float x, float y) {
    u64 r;
    asm("mov.b64 %0, {%1, %2};" : "=l"(r) : "f"(x), "f"(y));
    return r;
}
__device__ __forceinline__ u64 dup2(float x) { return pk2(x, x); }
__device__ __forceinline__ u64 ffma2(u64 a, u64 b, u64 c) {
    u64 d;
    asm("fma.rn.f32x2 %0, %1, %2, %3;" : "=l"(d) : "l"(a), "l"(b), "l"(c));
    return d;
}
__device__ __forceinline__ float2 up2(u64 v) {
    float2 f;
    asm("mov.b64 {%0, %1}, %2;" : "=f"(f.x), "=f"(f.y) : "l"(v));
    return f;
}

// ---------------------------------------------------------------------------
// mma helper: D(f32) += A(bf16 16x16) * B(bf16 16x8)
// ---------------------------------------------------------------------------
__device__ __forceinline__ void mma16816(float* c, const u32* a, const u32* b) {
    asm volatile(
        "mma.sync.aligned.m16n8k16.row.col.f32.bf16.bf16.f32 "
        "{%0,%1,%2,%3},{%4,%5,%6,%7},{%8,%9},{%0,%1,%2,%3};"
        : "+f"(c[0]), "+f"(c[1]), "+f"(c[2]), "+f"(c[3])
        : "r"(a[0]), "r"(a[1]), "r"(a[2]), "r"(a[3]), "r"(b[0]), "r"(b[1]));
}

__device__ __forceinline__ void cp16(u32 smem_addr, const void* gptr) {
    asm volatile("cp.async.cg.shared.global [%0], [%1], 16;"
                 :: "r"(smem_addr), "l"(gptr));
}

// ---------------------------------------------------------------------------
// split: src fp32 -> hi/lo bf16 (elementwise)
// ---------------------------------------------------------------------------
__global__ __launch_bounds__(256) void split_kernel(const float* __restrict__ src,
                                                    bf16* __restrict__ hi,
                                                    bf16* __restrict__ lo) {
    int i = (blockIdx.x * 256 + threadIdx.x) * 4;
    float4 v = *(const float4*)(src + i);
    bf16 h0 = __float2bfloat16(v.x);
    bf16 h1 = __float2bfloat16(v.y);
    bf16 h2 = __float2bfloat16(v.z);
    bf16 h3 = __float2bfloat16(v.w);
    bf16 l0 = __float2bfloat16(v.x - __bfloat162float(h0));
    bf16 l1 = __float2bfloat16(v.y - __bfloat162float(h1));
    bf16 l2 = __float2bfloat16(v.z - __bfloat162float(h2));
    bf16 l3 = __float2bfloat16(v.w - __bfloat162float(h3));
    __nv_bfloat162* hp = (__nv_bfloat162*)(hi + i);
    __nv_bfloat162* lp = (__nv_bfloat162*)(lo + i);
    hp[0] = __nv_bfloat162(h0, h1);
    hp[1] = __nv_bfloat162(h2, h3);
    lp[0] = __nv_bfloat162(l0, l1);
    lp[1] = __nv_bfloat162(l2, l3);
}

// ---------------------------------------------------------------------------
// splitT: W[K][N] fp32 -> transposed hi/lo bf16 [N][K]
// ---------------------------------------------------------------------------
__global__ void splitT_kernel(const float* __restrict__ W,
                              bf16* __restrict__ th, bf16* __restrict__ tl) {
    __shared__ float ts[32][33];
    const int tx = threadIdx.x, ty = threadIdx.y;
    const int n0 = blockIdx.x * 32, k0 = blockIdx.y * 32;
    for (int r = ty; r < 32; r += 8)
        ts[r][tx] = W[(size_t)(k0 + r) * D + n0 + tx];
    __syncthreads();
    for (int r = ty; r < 32; r += 8) {
        float v = ts[tx][r];
        bf16 h = __float2bfloat16(v);
        bf16 l = __float2bfloat16(v - __bfloat162float(h));
        th[(size_t)(n0 + r) * D + k0 + tx] = h;
        tl[(size_t)(n0 + r) * D + k0 + tx] = l;
    }
}

// ---------------------------------------------------------------------------
// hgemm3x: C[M,N] = alpha * A[M,K] @ B[K,N]  (A hi/lo bf16 row-major,
// B hi/lo bf16 transposed [N][K]). 3-pass compensated bf16 MMA.
// CTA tile 128x128, BK=16, 8 warps (warp tile 64x32), double-buffered cp.async.
// (unchanged from Round 5 — known-good at 855us total)
// ---------------------------------------------------------------------------
__global__ __launch_bounds__(256) void hgemm3x(const bf16* __restrict__ Ah,
                                               const bf16* __restrict__ Al,
                                               const bf16* __restrict__ Bh,
                                               const bf16* __restrict__ Bl,
                                               float* __restrict__ C,
                                               int Md, int Nd, int Kd,
                                               float alpha) {
    constexpr int STR = 24;
    constexpr int STG = 128 * STR;
    __shared__ bf16 As_h[2 * STG];
    __shared__ bf16 As_l[2 * STG];
    __shared__ bf16 Bs_h[2 * STG];
    __shared__ bf16 Bs_l[2 * STG];

    const int tid = threadIdx.x;
    const int bm = blockIdx.y * 128;
    const int bn = blockIdx.x * 128;
    const int wid = tid >> 5;
    const int lane = tid & 31;
    const int g = lane >> 2;
    const int tg = lane & 3;
    const int wm = (wid & 1) * 64;
    const int wn = (wid >> 1) * 32;

    const int lrow = tid >> 1;
    const int lseg = (tid & 1) * 8;
    const size_t aoff = (size_t)(bm + lrow) * Kd + lseg;
    const size_t boff = (size_t)(bn + lrow) * Kd + lseg;
    const u32 sdst = (u32)(lrow * STR + lseg) * 2;
    const u32 s_ah = (u32)__cvta_generic_to_shared(As_h);
    const u32 s_al = (u32)__cvta_generic_to_shared(As_l);
    const u32 s_bh = (u32)__cvta_generic_to_shared(Bs_h);
    const u32 s_bl = (u32)__cvta_generic_to_shared(Bs_l);

    float acc[4][4][4];
#pragma unroll
    for (int ma = 0; ma < 4; ++ma)
#pragma unroll
        for (int na = 0; na < 4; ++na)
#pragma unroll
            for (int e = 0; e < 4; ++e) acc[ma][na][e] = 0.0f;

    const int nT = Kd / 16;

    {
        const u32 o = sdst;
        cp16(s_ah + o, Ah + aoff);
        cp16(s_al + o, Al + aoff);
        cp16(s_bh + o, Bh + boff);
        cp16(s_bl + o, Bl + boff);
        asm volatile("cp.async.commit_group;");
    }

    for (int kt = 0; kt < nT; ++kt) {
        const int stg = kt & 1;
        if (kt + 1 < nT) {
            const u32 o = (u32)((stg ^ 1) * STG * 2) + sdst;
            const size_t ko = (size_t)(kt + 1) * 16;
            cp16(s_ah + o, Ah + aoff + ko);
            cp16(s_al + o, Al + aoff + ko);
            cp16(s_bh + o, Bh + boff + ko);
            cp16(s_bl + o, Bl + boff + ko);
            asm volatile("cp.async.commit_group;");
            asm volatile("cp.async.wait_group 1;");
        } else {
            asm volatile("cp.async.wait_group 0;");
        }
        __syncthreads();

        const bf16* Abh = As_h + stg * STG;
        const bf16* Abl = As_l + stg * STG;
        const bf16* Bbh = Bs_h + stg * STG;
        const bf16* Bbl = Bs_l + stg * STG;

        u32 ah[4][4], al[4][4], bh[4][2], bl[4][2];
#pragma unroll
        for (int ma = 0; ma < 4; ++ma) {
            const int r0 = (wm + ma * 16 + g) * STR + 2 * tg;
            const int r1 = r0 + 8 * STR;
            ah[ma][0] = *(const u32*)(Abh + r0);
            ah[ma][1] = *(const u32*)(Abh + r1);
            ah[ma][2] = *(const u32*)(Abh + r0 + 8);
            ah[ma][3] = *(const u32*)(Abh + r1 + 8);
            al[ma][0] = *(const u32*)(Abl + r0);
            al[ma][1] = *(const u32*)(Abl + r1);
            al[ma][2] = *(const u32*)(Abl + r0 + 8);
            al[ma][3] = *(const u32*)(Abl + r1 + 8);
        }
#pragma unroll
        for (int na = 0; na < 4; ++na) {
            const int c0 = (wn + na * 8 + g) * STR + 2 * tg;
            bh[na][0] = *(const u32*)(Bbh + c0);
            bh[na][1] = *(const u32*)(Bbh + c0 + 8);
            bl[na][0] = *(const u32*)(Bbl + c0);
            bl[na][1] = *(const u32*)(Bbl + c0 + 8);
        }

#pragma unroll
        for (int ma = 0; ma < 4; ++ma)
#pragma unroll
            for (int na = 0; na < 4; ++na)
                mma16816(acc[ma][na], ah[ma], bh[na]);
#pragma unroll
        for (int ma = 0; ma < 4; ++ma)
#pragma unroll
            for (int na = 0; na < 4; ++na)
                mma16816(acc[ma][na], ah[ma], bl[na]);
#pragma unroll
        for (int ma = 0; ma < 4; ++ma)
#pragma unroll
            for (int na = 0; na < 4; ++na)
                mma16816(acc[ma][na], al[ma], bh[na]);
        __syncthreads();
    }

#pragma unroll
    for (int ma = 0; ma < 4; ++ma) {
#pragma unroll
        for (int na = 0; na < 4; ++na) {
            const int r0 = bm + wm + ma * 16 + g;
            const int c = bn + wn + na * 8 + 2 * tg;
            *(float2*)(C + (size_t)r0 * Nd + c) =
                make_float2(acc[ma][na][0] * alpha, acc[ma][na][1] * alpha);
            *(float2*)(C + (size_t)(r0 + 8) * Nd + c) =
                make_float2(acc[ma][na][2] * alpha, acc[ma][na][3] * alpha);
        }
    }
}

// ---------------------------------------------------------------------------
// relq[bh,i,r] = q[bh,i,:] . rel_k_table[r,:]   (unchanged)
// ---------------------------------------------------------------------------
__global__ __launch_bounds__(256) void relq_kernel(const float* __restrict__ relk) {
    __shared__ __align__(16) float qsT[64][36];
    __shared__ __align__(16) float tsT[64][132];

    const int tid = threadIdx.x;
    const int bh = blockIdx.y;
    const int b = bh >> 4;
    const int h = bh & 15;
    const int i0 = blockIdx.x * 32;
    const int tx = tid & 31;
    const int ty = tid >> 5;

    {
        const int rI = tid >> 3;
        const int seg = (tid & 7) * 8;
        const float* qb = g_q + (size_t)(b * L + i0 + rI) * D + h * DH + seg;
        float4 v0 = *(const float4*)qb;
        float4 v1 = *(const float4*)(qb + 4);
        qsT[seg + 0][rI] = v0.x; qsT[seg + 1][rI] = v0.y;
        qsT[seg + 2][rI] = v0.z; qsT[seg + 3][rI] = v0.w;
        qsT[seg + 4][rI] = v1.x; qsT[seg + 5][rI] = v1.y;
        qsT[seg + 6][rI] = v1.z; qsT[seg + 7][rI] = v1.w;
    }
    for (int e = tid; e < R * 64; e += 256) {
        int r = e >> 6, d = e & 63;
        tsT[d][r] = relk[e];
    }
    __syncthreads();

    u64 acc2[2][4];
#pragma unroll
    for (int p = 0; p < 2; ++p)
#pragma unroll
        for (int j = 0; j < 4; ++j) acc2[p][j] = 0ull;

#pragma unroll 8
    for (int d = 0; d < 64; ++d) {
        const u64* ap = (const u64*)&qsT[d][ty * 4];
        u64 pa0 = ap[0], pa1 = ap[1];
        float4 bv = *(const float4*)&tsT[d][tx * 4];
        u64 pb0 = dup2(bv.x), pb1 = dup2(bv.y), pb2 = dup2(bv.z), pb3 = dup2(bv.w);
        acc2[0][0] = ffma2(pa0, pb0, acc2[0][0]);
        acc2[0][1] = ffma2(pa0, pb1, acc2[0][1]);
        acc2[0][2] = ffma2(pa0, pb2, acc2[0][2]);
        acc2[0][3] = ffma2(pa0, pb3, acc2[0][3]);
        acc2[1][0] = ffma2(pa1, pb0, acc2[1][0]);
        acc2[1][1] = ffma2(pa1, pb1, acc2[1][1]);
        acc2[1][2] = ffma2(pa1, pb2, acc2[1][2]);
        acc2[1][3] = ffma2(pa1, pb3, acc2[1][3]);
    }

#pragma unroll
    for (int p = 0; p < 2; ++p) {
        float2 c0 = up2(acc2[p][0]);
        float2 c1 = up2(acc2[p][1]);
        float2 c2 = up2(acc2[p][2]);
        float2 c3 = up2(acc2[p][3]);
        int gi = i0 + ty * 4 + 2 * p;
        float* o0 = g_relq + ((size_t)bh * L + gi) * RP + tx * 4;
        float* o1 = o0 + RP;
        *(float4*)o0 = make_float4(c0.x, c1.x, c2.x, c3.x);
        *(float4*)o1 = make_float4(c0.y, c1.y, c2.y, c3.y);
    }

    if (tid < 32) {
        float s = 0.0f;
#pragma unroll 8
        for (int d = 0; d < 64; ++d) s += qsT[d][tid] * tsT[d][128];
        g_relq[((size_t)bh * L + i0 + tid) * RP + 128] = s;
    }
}

// ---------------------------------------------------------------------------
// NEW fused kernel: logits + softmax + wsum for one (bh, 32-row i-block).
// grid (L/32=32, BH=32) = 1024 CTAs, 256 threads, ~188KB dynamic smem.
//   - Q block + bias rows staged once
//   - K streamed in 8 chunks of 128 rows (register-prefetch pipelined)
//   - f32x2 microkernel: thread = 4i x 4j per chunk
//   - full rows in smem -> max/exp/sum -> normalized w to g_s + wsum
// ---------------------------------------------------------------------------
namespace {
constexpr int SBS = 1032;  // Sb row stride (floats)
constexpr u32 FUSED_SMEM_FLOATS = 32 * SBS      // Sb
                                  + 64 * 132    // KsT
                                  + 64 * 36     // QsT
                                  + 32 * 132    // biasS
                                  + 32;         // invS
constexpr u32 FUSED_SMEM = FUSED_SMEM_FLOATS * 4;  // 192,128 B
}

__global__ __launch_bounds__(256, 1) void fused_sm_kernel() {
    extern __shared__ float fs[];
    float* Sb    = fs;                       // [32][SBS]
    float* KsT   = Sb + 32 * SBS;            // [64][132] (d-major, j contiguous)
    float* QsT   = KsT + 64 * 132;           // [64][36]  (d-major, i contiguous)
    float* biasS = QsT + 64 * 36;            // [32][132]
    float* invS  = biasS + 32 * 132;         // [32]

    const int tid = threadIdx.x;
    const int bh = blockIdx.y;
    const int b = bh >> 4;
    const int h = bh & 15;
    const int i0 = blockIdx.x * 32;

    // stage QsT (32 rows x 64 d, transposed)
    {
        const int rI = tid >> 3;            // 0..31
        const int seg = (tid & 7) * 8;      // 0..56
        const float* qb = g_q + (size_t)(b * L + i0 + rI) * D + h * DH + seg;
        float4 v0 = *(const float4*)qb;
        float4 v1 = *(const float4*)(qb + 4);
        QsT[(seg + 0) * 36 + rI] = v0.x; QsT[(seg + 1) * 36 + rI] = v0.y;
        QsT[(seg + 2) * 36 + rI] = v0.z; QsT[(seg + 3) * 36 + rI] = v0.w;
        QsT[(seg + 4) * 36 + rI] = v1.x; QsT[(seg + 5) * 36 + rI] = v1.y;
        QsT[(seg + 6) * 36 + rI] = v1.z; QsT[(seg + 7) * 36 + rI] = v1.w;
    }
    // stage bias rows (relq), 129 valid entries per row
    for (int e = tid; e < 32 * 132; e += 256) {
        int il = e / 132, r = e - il * 132;
        biasS[e] = (r < R) ? g_relq[((size_t)bh * L + i0 + il) * RP + r] : 0.0f;
    }

    const int ty = tid >> 5;            // 0..7  -> 4 i rows
    const int tx = tid & 31;            // 0..31 -> 4 j cols
    const int rJ = tid >> 1;            // 0..127 (K staging row within chunk)
    const int segk = (tid & 1) * 32;    // 0 or 32
    const float* kbase = g_k + (size_t)(b * L + rJ) * D + h * DH + segk;

    float4 kreg[8];
#pragma unroll
    for (int u = 0; u < 8; ++u) kreg[u] = *(const float4*)(kbase + 4 * u);
    __syncthreads();   // QsT/biasS staged

    for (int jc = 0; jc < 8; ++jc) {
        // scatter prefetched K chunk into transposed KsT
#pragma unroll
        for (int u = 0; u < 8; ++u) {
            int c = segk + 4 * u;
            KsT[(c + 0) * 132 + rJ] = kreg[u].x;
            KsT[(c + 1) * 132 + rJ] = kreg[u].y;
            KsT[(c + 2) * 132 + rJ] = kreg[u].z;
            KsT[(c + 3) * 132 + rJ] = kreg[u].w;
        }
        __syncthreads();
        if (jc < 7) {
            const float* kb = kbase + (size_t)(jc + 1) * 128 * D;
#pragma unroll
            for (int u = 0; u < 8; ++u) kreg[u] = *(const float4*)(kb + 4 * u);
        }

        u64 acc2[2][4];
#pragma unroll
        for (int p = 0; p < 2; ++p)
#pragma unroll
            for (int j = 0; j < 4; ++j) acc2[p][j] = 0ull;

#pragma unroll 8
        for (int d = 0; d < 64; ++d) {
            const u64* ap = (const u64*)&QsT[d * 36 + ty * 4];
            u64 pa0 = ap[0], pa1 = ap[1];
            float4 bv = *(const float4*)&KsT[d * 132 + tx * 4];
            u64 pb0 = dup2(bv.x), pb1 = dup2(bv.y);
            u64 pb2 = dup2(bv.z), pb3 = dup2(bv.w);
            acc2[0][0] = ffma2(pa0, pb0, acc2[0][0]);
            acc2[0][1] = ffma2(pa0, pb1, acc2[0][1]);
            acc2[0][2] = ffma2(pa0, pb2, acc2[0][2]);
            acc2[0][3] = ffma2(pa0, pb3, acc2[0][3]);
            acc2[1][0] = ffma2(pa1, pb0, acc2[1][0]);
            acc2[1][1] = ffma2(pa1, pb1, acc2[1][1]);
            acc2[1][2] = ffma2(pa1, pb2, acc2[1][2]);
            acc2[1][3] = ffma2(pa1, pb3, acc2[1][3]);
        }

        const int jb = jc * 128 + tx * 4;
#pragma unroll
        for (int p = 0; p < 2; ++p) {
            float2 c0 = up2(acc2[p][0]);
            float2 c1 = up2(acc2[p][1]);
            float2 c2 = up2(acc2[p][2]);
            float2 c3 = up2(acc2[p][3]);
#pragma unroll
            for (int e = 0; e < 2; ++e) {
                const int il = ty * 4 + 2 * p + e;
                const int gi = i0 + il;
                const float* brow = biasS + il * 132;
                int r0 = min(max(jb + 0 - gi, -MREL), MREL) + MREL;
                int r1 = min(max(jb + 1 - gi, -MREL), MREL) + MREL;
                int r2 = min(max(jb + 2 - gi, -MREL), MREL) + MREL;
                int r3 = min(max(jb + 3 - gi, -MREL), MREL) + MREL;
                float4 o;
                o.x = (e ? c0.y : c0.x) + brow[r0];
                o.y = (e ? c1.y : c1.x) + brow[r1];
                o.z = (e ? c2.y : c2.x) + brow[r2];
                o.w = (e ? c3.y : c3.x) + brow[r3];
                *(float4*)&Sb[il * SBS + jb] = o;
            }
        }
        __syncthreads();   // KsT reusable next iter; Sb visible after loop
    }

    // ---- softmax over full rows (8 threads per row) ----
    const int row = tid >> 3;     // 0..31
    const int ts = tid & 7;
    const int gi = i0 + row;
    float* srow = Sb + row * SBS;

    float m = -3.0e38f;
#pragma unroll 8
    for (int c = 0; c < 32; ++c) {
        float4 v = *(const float4*)&srow[ts * 4 + c * 32];
        m = fmaxf(m, fmaxf(fmaxf(v.x, v.y), fmaxf(v.z, v.w)));
    }
#pragma unroll
    for (int o = 4; o > 0; o >>= 1) m = fmaxf(m, __shfl_xor_sync(0xffffffffu, m, o));

    float s = 0.0f;
#pragma unroll 8
    for (int c = 0; c < 32; ++c) {
        float4 v = *(float4*)&srow[ts * 4 + c * 32];
        v.x = __expf(v.x - m); v.y = __expf(v.y - m);
        v.z = __expf(v.z - m); v.w = __expf(v.w - m);
        *(float4*)&srow[ts * 4 + c * 32] = v;
        s += v.x + v.y + v.z + v.w;
    }
#pragma unroll
    for (int o = 4; o > 0; o >>= 1) s += __shfl_xor_sync(0xffffffffu, s, o);
    const float inv = 1.0f / s;
    if (ts == 0) invS[row] = inv;

    // wsum band r = 1..127 : w[gi + r - 64]
    float* wrow_g = g_wsum + ((size_t)bh * L + gi) * RP;
#pragma unroll
    for (int k = 0; k < 16; ++k) {
        int r = 1 + ts * 16 + k;
        if (r < 128) {
            int j = gi + r - 64;
            wrow_g[r] = (j >= 0 && j < L) ? srow[j] * inv : 0.0f;
        }
    }
    // head (r=0) and tail (r=128)
    float hp = 0.0f, tp = 0.0f;
    for (int j = ts; j <= gi - MREL; j += 8) hp += srow[j];
    for (int j = gi + MREL + ts; j < L; j += 8) tp += srow[j];
#pragma unroll
    for (int o = 4; o > 0; o >>= 1) {
        hp += __shfl_xor_sync(0xffffffffu, hp, o);
        tp += __shfl_xor_sync(0xffffffffu, tp, o);
    }
    if (ts == 0) {
        wrow_g[0] = hp * inv;
        wrow_g[128] = tp * inv;
    }

    __syncthreads();   // invS visible to all warps

    // ---- coalesced normalized write of w rows to g_s ----
    const int wwarp = tid >> 5;
    const int lane = tid & 31;
    for (int rr = wwarp; rr < 32; rr += 8) {
        const float iv = invS[rr];
        const float* sr = Sb + rr * SBS;
        float* gout = g_s + ((size_t)bh * L + i0 + rr) * L;
#pragma unroll
        for (int it = 0; it < 8; ++it) {
            float4 v = *(const float4*)&sr[it * 128 + lane * 4];
            v.x *= iv; v.y *= iv; v.z *= iv; v.w *= iv;
            *(float4*)&gout[it * 128 + lane * 4] = v;
        }
    }
}

// ---------------------------------------------------------------------------
// Attention output: O = W@V + wsum@rel_v_table  (unchanged)
// ---------------------------------------------------------------------------
__global__ __launch_bounds__(256) void attnout_kernel(const float* __restrict__ relv) {
    __shared__ __align__(16) float Ws[64][68];
    __shared__ __align__(16) float Vs[64][68];

    const int tid = threadIdx.x;
    const int bh = blockIdx.y;
    const int b = bh >> 4;
    const int h = bh & 15;
    const int i0 = blockIdx.x * 64;
    const int tx = tid & 31;
    const int ty = tid >> 5;

    const int rI = tid >> 2;
    const int seg = (tid & 3) * 16;

    u64 acc2[4][2];
#pragma unroll
    for (int p = 0; p < 4; ++p) { acc2[p][0] = 0ull; acc2[p][1] = 0ull; }

    for (int k0 = 0; k0 < L; k0 += 64) {
        const float* wb = g_s + ((size_t)bh * L + i0 + rI) * L + k0 + seg;
#pragma unroll
        for (int u = 0; u < 4; ++u) {
            float4 v = *(const float4*)(wb + 4 * u);
            int c = seg + 4 * u;
            Ws[c + 0][rI] = v.x; Ws[c + 1][rI] = v.y;
            Ws[c + 2][rI] = v.z; Ws[c + 3][rI] = v.w;
        }
        const float* vb = g_v + (size_t)(b * L + k0 + rI) * D + h * DH + seg;
#pragma unroll
        for (int u = 0; u < 4; ++u)
            *(float4*)&Vs[rI][seg + 4 * u] = *(const float4*)(vb + 4 * u);
        __syncthreads();

#pragma unroll 8
        for (int k = 0; k < 64; ++k) {
            const u64* ap = (const u64*)&Ws[k][ty * 8];
            u64 pa0 = ap[0], pa1 = ap[1], pa2 = ap[2], pa3 = ap[3];
            float2 bv = *(const float2*)&Vs[k][tx * 2];
            u64 pb0 = dup2(bv.x), pb1 = dup2(bv.y);
            acc2[0][0] = ffma2(pa0, pb0, acc2[0][0]);
            acc2[0][1] = ffma2(pa0, pb1, acc2[0][1]);
            acc2[1][0] = ffma2(pa1, pb0, acc2[1][0]);
            acc2[1][1] = ffma2(pa1, pb1, acc2[1][1]);
            acc2[2][0] = ffma2(pa2, pb0, acc2[2][0]);
            acc2[2][1] = ffma2(pa2, pb1, acc2[2][1]);
            acc2[3][0] = ffma2(pa3, pb0, acc2[3][0]);
            acc2[3][1] = ffma2(pa3, pb1, acc2[3][1]);
        }
        __syncthreads();
    }

    const float* wsbase = g_wsum + ((size_t)bh * L + i0 + ty * 8) * RP;
    for (int r = 0; r < R; ++r) {
        float2 tv = __ldg((const float2*)(relv + r * DH + tx * 2));
        u64 pt0 = dup2(tv.x), pt1 = dup2(tv.y);
#pragma unroll
        for (int p = 0; p < 4; ++p) {
            float w0 = __ldg(wsbase + (size_t)(2 * p) * RP + r);
            float w1 = __ldg(wsbase + (size_t)(2 * p + 1) * RP + r);
            u64 pw = pk2(w0, w1);
            acc2[p][0] = ffma2(pw, pt0, acc2[p][0]);
            acc2[p][1] = ffma2(pw, pt1, acc2[p][1]);
        }
    }

#pragma unroll
    for (int p = 0; p < 4; ++p) {
        float2 c0 = up2(acc2[p][0]);
        float2 c1 = up2(acc2[p][1]);
        int gi = i0 + ty * 8 + 2 * p;
        float* o0 = g_o + (size_t)(b * L + gi) * D + h * DH + tx * 2;
        float* o1 = o0 + D;
        *(float2*)o0 = make_float2(c0.x, c1.x);
        *(float2*)o1 = make_float2(c0.y, c1.y);
    }
}

// ---------------------------------------------------------------------------
// Launch
// ---------------------------------------------------------------------------
extern "C" void kernel_launch(void* const* d_in, const int* in_sizes, int n_in,
                              void* d_out, int out_size) {
    const float* x    = (const float*)d_in[0];
    const float* Wq   = (const float*)d_in[1];
    const float* Wk   = (const float*)d_in[2];
    const float* Wv   = (const float*)d_in[3];
    const float* Wo   = (const float*)d_in[4];
    const float* relk = (const float*)d_in[5];
    const float* relv = (const float*)d_in[6];
    float* out = (float*)d_out;

    float *pq, *pk, *pv, *po;
    cudaGetSymbolAddress((void**)&pq, g_q);
    cudaGetSymbolAddress((void**)&pk, g_k);
    cudaGetSymbolAddress((void**)&pv, g_v);
    cudaGetSymbolAddress((void**)&po, g_o);
    bf16 *xh, *xl, *wh, *wl;
    cudaGetSymbolAddress((void**)&xh, g_xh);
    cudaGetSymbolAddress((void**)&xl, g_xl);
    cudaGetSymbolAddress((void**)&wh, g_wh);
    cudaGetSymbolAddress((void**)&wl, g_wl);

    cudaFuncSetAttribute(fused_sm_kernel,
                         cudaFuncAttributeMaxDynamicSharedMemorySize,
                         (int)FUSED_SMEM);

    const dim3 gg(D / 128, NT / 128);       // (8, 16) = 128 CTAs
    const dim3 gt(32, 32);
    const dim3 bt(32, 8);
    const int splitBlocks = (NT * D) / (256 * 4);   // 2048
    const float qscale = 0.125f;            // DH^-0.5

    // x split once, reused for q/k/v
    split_kernel<<<splitBlocks, 256>>>(x, xh, xl);

    splitT_kernel<<<gt, bt>>>(Wq, wh, wl);
    hgemm3x<<<gg, 256>>>(xh, xl, wh, wl, pq, NT, D, D, qscale);

    splitT_kernel<<<gt, bt>>>(Wk, wh, wl);
    hgemm3x<<<gg, 256>>>(xh, xl, wh, wl, pk, NT, D, D, 1.0f);

    splitT_kernel<<<gt, bt>>>(Wv, wh, wl);
    hgemm3x<<<gg, 256>>>(xh, xl, wh, wl, pv, NT, D, D, 1.0f);

    relq_kernel<<<dim3(L / 32, BH), 256>>>(relk);

    // fused logits + softmax + wsum
    fused_sm_kernel<<<dim3(L / 32, BH), 256, FUSED_SMEM>>>();

    attnout_kernel<<<dim3(L / 64, BH), 256>>>(relv);

    // final projection
    split_kernel<<<splitBlocks, 256>>>(po, xh, xl);
    splitT_kernel<<<gt, bt>>>(Wo, wh, wl);
    hgemm3x<<<gg, 256>>>(xh, xl, wh, wl, out, NT, D, D, 1.0f);
}